// round 10
// baseline (speedup 1.0000x reference)
#include <cuda_runtime.h>
#include <cuda_bf16.h>
#include <cfloat>
#include <math.h>

// ---------------- problem constants ----------------
#define BB 8
#define NN 2048
#define KK 20
#define PP 64
#define PS 32
#define DD 1024
#define TOK (BB * (PP + 1))   // 520
#define INNER 512
#define MLPD 2048
#define EROWS (BB * NN * KK)  // 327680
#define RBLK (EROWS / 128)    // 2560

// ---------------- scratch ----------------
__device__ float g_h[BB * NN * 512];
__device__ float g_G[BB * NN * NN];
__device__ float g_sq[BB * NN];
__device__ int   g_knn[EROWS];
__device__ float g_ey[(size_t)EROWS * 256];
__device__ float g_psum[RBLK * 256];
__device__ float g_psq[RBLK * 256];
__device__ float g_mean[1024];
__device__ float g_rstd[1024];
__device__ float g_y5[BB * NN * DD];
__device__ float g_t[TOK * DD];
__device__ float g_ln[TOK * DD];
__device__ float g_qkv[TOK * 3 * INNER];
__device__ float g_z[TOK * INNER];
__device__ float g_ff[TOK * MLPD];

__device__ __forceinline__ float4 ld4(const float* p) { return *(const float4*)p; }

// ================= double-buffered 128x128x16 SGEMM (gram / conv5) =================
template <bool TRANSB, int ACT, bool ADDC>
__global__ __launch_bounds__(256, 2)
void gemm128(const float* __restrict__ A, int lda, size_t strideA,
             const float* __restrict__ Bm, int ldb, size_t strideB,
             const float* __restrict__ bias,
             float* __restrict__ C, int ldc, size_t strideC,
             int M, int N, int K)
{
    const int BK = 16;
    __shared__ float As[2][BK][128];
    __shared__ float Bs[2][BK][128];
    A  += (size_t)blockIdx.z * strideA;
    Bm += (size_t)blockIdx.z * strideB;
    C  += (size_t)blockIdx.z * strideC;
    int bm = blockIdx.y * 128, bn = blockIdx.x * 128;
    int tid = threadIdx.x;
    int trow = tid >> 4, tcol = tid & 15;

    float4 ra[2], rb[2];

    auto loadA = [&](int k0) {
#pragma unroll
        for (int i = 0; i < 2; i++) {
            int row = i * 64 + (tid >> 2), q = tid & 3;
            int gm = bm + row, gk = k0 + q * 4;
            if (k0 + BK <= K) {
                ra[i] = (gm < M) ? ld4(&A[(size_t)gm * lda + gk]) : make_float4(0, 0, 0, 0);
            } else {
                float v[4];
#pragma unroll
                for (int j = 0; j < 4; j++)
                    v[j] = (gm < M && gk + j < K) ? A[(size_t)gm * lda + gk + j] : 0.f;
                ra[i] = make_float4(v[0], v[1], v[2], v[3]);
            }
        }
    };
    auto loadB = [&](int k0) {
#pragma unroll
        for (int i = 0; i < 2; i++) {
            if (TRANSB) {
                int row = i * 64 + (tid >> 2), q = tid & 3;
                int gn = bn + row, gk = k0 + q * 4;
                if (k0 + BK <= K) {
                    rb[i] = (gn < N) ? ld4(&Bm[(size_t)gn * ldb + gk]) : make_float4(0, 0, 0, 0);
                } else {
                    float v[4];
#pragma unroll
                    for (int j = 0; j < 4; j++)
                        v[j] = (gn < N && gk + j < K) ? Bm[(size_t)gn * ldb + gk + j] : 0.f;
                    rb[i] = make_float4(v[0], v[1], v[2], v[3]);
                }
            } else {
                int krow = i * 8 + (tid >> 5), nq = tid & 31;
                int gk = k0 + krow, gn = bn + nq * 4;
                if (gk < K && gn < N) rb[i] = ld4(&Bm[(size_t)gk * ldb + gn]);
                else rb[i] = make_float4(0, 0, 0, 0);
            }
        }
    };
    auto storeA = [&](int p) {
#pragma unroll
        for (int i = 0; i < 2; i++) {
            int row = i * 64 + (tid >> 2), q = tid & 3;
            As[p][q * 4 + 0][row] = ra[i].x;
            As[p][q * 4 + 1][row] = ra[i].y;
            As[p][q * 4 + 2][row] = ra[i].z;
            As[p][q * 4 + 3][row] = ra[i].w;
        }
    };
    auto storeB = [&](int p) {
#pragma unroll
        for (int i = 0; i < 2; i++) {
            if (TRANSB) {
                int row = i * 64 + (tid >> 2), q = tid & 3;
                Bs[p][q * 4 + 0][row] = rb[i].x;
                Bs[p][q * 4 + 1][row] = rb[i].y;
                Bs[p][q * 4 + 2][row] = rb[i].z;
                Bs[p][q * 4 + 3][row] = rb[i].w;
            } else {
                int krow = i * 8 + (tid >> 5), nq = tid & 31;
                *(float4*)&Bs[p][krow][nq * 4] = rb[i];
            }
        }
    };

    float acc[8][8];
#pragma unroll
    for (int i = 0; i < 8; i++)
#pragma unroll
        for (int j = 0; j < 8; j++) acc[i][j] = 0.f;

    int nk = (K + BK - 1) / BK;
    loadA(0); loadB(0);
    storeA(0); storeB(0);
    __syncthreads();
    int p = 0;
    for (int it = 0; it < nk; it++) {
        if (it + 1 < nk) { loadA((it + 1) * BK); loadB((it + 1) * BK); }
#pragma unroll
        for (int k = 0; k < BK; k++) {
            float4 a0 = ld4(&As[p][k][trow * 8]);
            float4 a1 = ld4(&As[p][k][trow * 8 + 4]);
            float4 b0 = ld4(&Bs[p][k][tcol * 8]);
            float4 b1 = ld4(&Bs[p][k][tcol * 8 + 4]);
            float a[8] = {a0.x, a0.y, a0.z, a0.w, a1.x, a1.y, a1.z, a1.w};
            float b[8] = {b0.x, b0.y, b0.z, b0.w, b1.x, b1.y, b1.z, b1.w};
#pragma unroll
            for (int i = 0; i < 8; i++)
#pragma unroll
                for (int j = 0; j < 8; j++) acc[i][j] += a[i] * b[j];
        }
        if (it + 1 < nk) { storeA(p ^ 1); storeB(p ^ 1); }
        __syncthreads();
        p ^= 1;
    }
#pragma unroll
    for (int i = 0; i < 8; i++) {
        int gm = bm + trow * 8 + i;
        if (gm >= M) continue;
#pragma unroll
        for (int j = 0; j < 8; j++) {
            int gn = bn + tcol * 8 + j;
            if (gn >= N) continue;
            float v = acc[i][j];
            if (bias) v += bias[gn];
            if (ACT == 1) v = 0.5f * v * (1.f + erff(v * 0.70710678118654752f));
            size_t off = (size_t)gm * ldc + gn;
            if (ADDC) v += C[off];
            C[off] = v;
        }
    }
}

// ================= double-buffered 64x64x32 SGEMM (transformer, B=[K,N]) =================
template <int ACT, bool ADDC>
__global__ __launch_bounds__(256)
void gemm64(const float* __restrict__ A, int lda,
            const float* __restrict__ Bm, int ldb,
            const float* __restrict__ bias,
            float* __restrict__ C, int ldc,
            int M, int N, int K)
{
    const int BK = 32;
    __shared__ float As[2][BK][64];
    __shared__ float Bs[2][BK][64];
    int bm = blockIdx.y * 64, bn = blockIdx.x * 64;
    int tid = threadIdx.x;
    int trow = tid >> 4, tcol = tid & 15;
    float4 ra[2], rb[2];

    auto loadA = [&](int k0) {
        int row = tid >> 2, q = tid & 3;
        int gm = bm + row, gk = k0 + q * 8;
        if (gm < M) {
            ra[0] = ld4(&A[(size_t)gm * lda + gk]);
            ra[1] = ld4(&A[(size_t)gm * lda + gk + 4]);
        } else {
            ra[0] = make_float4(0, 0, 0, 0);
            ra[1] = make_float4(0, 0, 0, 0);
        }
    };
    auto loadB = [&](int k0) {
        int krow = tid >> 3, gn = bn + (tid & 7) * 8;
        int gk = k0 + krow;
        rb[0] = ld4(&Bm[(size_t)gk * ldb + gn]);
        rb[1] = ld4(&Bm[(size_t)gk * ldb + gn + 4]);
    };
    auto storeA = [&](int p) {
        int row = tid >> 2, q = tid & 3;
#pragma unroll
        for (int i = 0; i < 2; i++) {
            As[p][q * 8 + i * 4 + 0][row] = (i ? ra[1].x : ra[0].x);
            As[p][q * 8 + i * 4 + 1][row] = (i ? ra[1].y : ra[0].y);
            As[p][q * 8 + i * 4 + 2][row] = (i ? ra[1].z : ra[0].z);
            As[p][q * 8 + i * 4 + 3][row] = (i ? ra[1].w : ra[0].w);
        }
    };
    auto storeB = [&](int p) {
        int krow = tid >> 3, nq = (tid & 7) * 8;
        *(float4*)&Bs[p][krow][nq] = rb[0];
        *(float4*)&Bs[p][krow][nq + 4] = rb[1];
    };

    float acc[4][4];
#pragma unroll
    for (int i = 0; i < 4; i++)
#pragma unroll
        for (int j = 0; j < 4; j++) acc[i][j] = 0.f;

    int nk = K / BK;
    loadA(0); loadB(0);
    storeA(0); storeB(0);
    __syncthreads();
    int p = 0;
    for (int it = 0; it < nk; it++) {
        if (it + 1 < nk) { loadA((it + 1) * BK); loadB((it + 1) * BK); }
#pragma unroll
        for (int k = 0; k < BK; k++) {
            float4 a4 = ld4(&As[p][k][trow * 4]);
            float4 b4 = ld4(&Bs[p][k][tcol * 4]);
            float a[4] = {a4.x, a4.y, a4.z, a4.w};
            float b[4] = {b4.x, b4.y, b4.z, b4.w};
#pragma unroll
            for (int i = 0; i < 4; i++)
#pragma unroll
                for (int j = 0; j < 4; j++) acc[i][j] += a[i] * b[j];
        }
        if (it + 1 < nk) { storeA(p ^ 1); storeB(p ^ 1); }
        __syncthreads();
        p ^= 1;
    }
#pragma unroll
    for (int i = 0; i < 4; i++) {
        int gm = bm + trow * 4 + i;
        if (gm >= M) continue;
#pragma unroll
        for (int j = 0; j < 4; j++) {
            int gn = bn + tcol * 4 + j;
            float v = acc[i][j];
            if (bias) v += bias[gn];
            if (ACT == 1) v = 0.5f * v * (1.f + erff(v * 0.70710678118654752f));
            size_t off = (size_t)gm * ldc + gn;
            if (ADDC) v += C[off];
            C[off] = v;
        }
    }
}

// ================= gather-fused EdgeConv GEMM + in-epilogue BN partials =================
template <int BN>
__global__ __launch_bounds__(256, 2)
void ec_gemm(const float* __restrict__ feat, int stride, int C,
             const int* __restrict__ knn,
             const float* __restrict__ w, int O,
             float* __restrict__ y,
             float* __restrict__ psum, float* __restrict__ psq)
{
    const int BK = 16;
    constexpr int TN = BN / 16;
    __shared__ float As[2][BK][128];
    __shared__ float Bs[2][BK][BN];
    __shared__ float red[16][BN];
    __shared__ int s_nbr[128], s_ctr[128];
    int tid = threadIdx.x;
    int bm = blockIdx.y * 128, bn0 = blockIdx.x * BN;
    int C2 = 2 * C;
    for (int i = tid; i < 128; i += 256) {
        int r = bm + i;
        int pnt = r / KK;
        int b = pnt >> 11;
        int j = knn[r];
        s_nbr[i] = ((b << 11) + j) * stride;
        s_ctr[i] = pnt * stride;
    }
    __syncthreads();
    int trow = tid >> 4, tcol = tid & 15;
    bool c4ok = ((C & 3) == 0);

    float4 ra[2], rb[BN / 64];

    auto loadA = [&](int k0) {
#pragma unroll
        for (int i = 0; i < 2; i++) {
            int row = i * 64 + (tid >> 2), q = tid & 3;
            int c4 = k0 + q * 4;
            if (k0 + BK <= C2 && c4ok) {
                if (c4 + 4 <= C) {
                    float4 nb = ld4(&feat[s_nbr[row] + c4]);
                    float4 ct = ld4(&feat[s_ctr[row] + c4]);
                    ra[i] = make_float4(nb.x - ct.x, nb.y - ct.y, nb.z - ct.z, nb.w - ct.w);
                } else {
                    ra[i] = ld4(&feat[s_ctr[row] + c4 - C]);
                }
            } else {
                float v[4];
#pragma unroll
                for (int j = 0; j < 4; j++) {
                    int c = c4 + j;
                    float xv = 0.f;
                    if (c < C2) {
                        if (c < C) xv = feat[s_nbr[row] + c] - feat[s_ctr[row] + c];
                        else       xv = feat[s_ctr[row] + c - C];
                    }
                    v[j] = xv;
                }
                ra[i] = make_float4(v[0], v[1], v[2], v[3]);
            }
        }
    };
    auto loadB = [&](int k0) {
#pragma unroll
        for (int i = 0; i < BN / 64; i++) {
            int row = i * 64 + (tid >> 2), q = tid & 3;
            int gn = bn0 + row, gk = k0 + q * 4;
            if (k0 + BK <= C2 && c4ok) {
                rb[i] = (gn < O) ? ld4(&w[(size_t)gn * C2 + gk]) : make_float4(0, 0, 0, 0);
            } else {
                float v[4];
#pragma unroll
                for (int j = 0; j < 4; j++)
                    v[j] = (gn < O && gk + j < C2) ? w[(size_t)gn * C2 + gk + j] : 0.f;
                rb[i] = make_float4(v[0], v[1], v[2], v[3]);
            }
        }
    };
    auto storeA = [&](int p) {
#pragma unroll
        for (int i = 0; i < 2; i++) {
            int row = i * 64 + (tid >> 2), q = tid & 3;
            As[p][q * 4 + 0][row] = ra[i].x;
            As[p][q * 4 + 1][row] = ra[i].y;
            As[p][q * 4 + 2][row] = ra[i].z;
            As[p][q * 4 + 3][row] = ra[i].w;
        }
    };
    auto storeB = [&](int p) {
#pragma unroll
        for (int i = 0; i < BN / 64; i++) {
            int row = i * 64 + (tid >> 2), q = tid & 3;
            Bs[p][q * 4 + 0][row] = rb[i].x;
            Bs[p][q * 4 + 1][row] = rb[i].y;
            Bs[p][q * 4 + 2][row] = rb[i].z;
            Bs[p][q * 4 + 3][row] = rb[i].w;
        }
    };

    float acc[8][TN];
#pragma unroll
    for (int i = 0; i < 8; i++)
#pragma unroll
        for (int j = 0; j < TN; j++) acc[i][j] = 0.f;

    int nk = (C2 + BK - 1) / BK;
    loadA(0); loadB(0);
    storeA(0); storeB(0);
    __syncthreads();
    int p = 0;
    for (int it = 0; it < nk; it++) {
        if (it + 1 < nk) { loadA((it + 1) * BK); loadB((it + 1) * BK); }
#pragma unroll
        for (int k = 0; k < BK; k++) {
            float a[8], b[TN];
            float4 a0 = ld4(&As[p][k][trow * 8]);
            float4 a1 = ld4(&As[p][k][trow * 8 + 4]);
            a[0] = a0.x; a[1] = a0.y; a[2] = a0.z; a[3] = a0.w;
            a[4] = a1.x; a[5] = a1.y; a[6] = a1.z; a[7] = a1.w;
#pragma unroll
            for (int j = 0; j < TN / 4; j++) {
                float4 b4 = ld4(&Bs[p][k][tcol * TN + j * 4]);
                b[j * 4 + 0] = b4.x; b[j * 4 + 1] = b4.y;
                b[j * 4 + 2] = b4.z; b[j * 4 + 3] = b4.w;
            }
#pragma unroll
            for (int i = 0; i < 8; i++)
#pragma unroll
                for (int j = 0; j < TN; j++) acc[i][j] += a[i] * b[j];
        }
        if (it + 1 < nk) { storeA(p ^ 1); storeB(p ^ 1); }
        __syncthreads();
        p ^= 1;
    }
#pragma unroll
    for (int i = 0; i < 8; i++) {
        int m = bm + trow * 8 + i;
#pragma unroll
        for (int j = 0; j < TN; j++) {
            int col = bn0 + tcol * TN + j;
            y[(size_t)m * O + col] = acc[i][j];
        }
    }
    // ----- deterministic per-block BN partials -----
    float cs[TN], cq[TN];
#pragma unroll
    for (int j = 0; j < TN; j++) {
        float s = 0.f, s2 = 0.f;
#pragma unroll
        for (int i = 0; i < 8; i++) { s += acc[i][j]; s2 += acc[i][j] * acc[i][j]; }
        cs[j] = s; cq[j] = s2;
    }
    size_t pbase = ((size_t)blockIdx.x * gridDim.y + blockIdx.y) * BN;
#pragma unroll
    for (int j = 0; j < TN; j++) red[trow][tcol * TN + j] = cs[j];
    __syncthreads();
    if (tid < BN) {
        float s = 0.f;
#pragma unroll
        for (int r = 0; r < 16; r++) s += red[r][tid];
        psum[pbase + tid] = s;
    }
    __syncthreads();
#pragma unroll
    for (int j = 0; j < TN; j++) red[trow][tcol * TN + j] = cq[j];
    __syncthreads();
    if (tid < BN) {
        float s = 0.f;
#pragma unroll
        for (int r = 0; r < 16; r++) s += red[r][tid];
        psq[pbase + tid] = s;
    }
}

// ---------------- deterministic BN finalize (strided partial layout) ----------------
__global__ void bn_reduce2(const float* __restrict__ psum, const float* __restrict__ psq,
                           int npart, int O, int bnsz, float cnt_inv,
                           float* __restrict__ mean, float* __restrict__ rstd)
{
    int o = blockIdx.x * blockDim.x + threadIdx.x;
    if (o >= O) return;
    int colblk = o / bnsz, c = o % bnsz;
    const float* ps = psum + (size_t)colblk * npart * bnsz + c;
    const float* pq = psq + (size_t)colblk * npart * bnsz + c;
    float s = 0.f, s2 = 0.f;
    for (int i = 0; i < npart; i++) {
        s  += ps[(size_t)i * bnsz];
        s2 += pq[(size_t)i * bnsz];
    }
    float mu = s * cnt_inv;
    float var = s2 * cnt_inv - mu * mu;
    mean[o] = mu;
    rstd[o] = rsqrtf(var + 1e-5f);
}

// ---------------- BN + lrelu + max over k ----------------
__global__ void ec_apply_y(const float* __restrict__ y, int O,
                           const float* __restrict__ mean, const float* __restrict__ rstd,
                           const float* __restrict__ gam, const float* __restrict__ bet,
                           float* __restrict__ outH, int outOff)
{
    int bn = blockIdx.x;
    int o = threadIdx.x;
    float mu = mean[o], rs = rstd[o], gg = gam[o], bb = bet[o];
    float m = -FLT_MAX;
    for (int kk = 0; kk < KK; kk++) {
        float v = y[((size_t)bn * KK + kk) * O + o];
        v = (v - mu) * rs * gg + bb;
        v = (v >= 0.f) ? v : 0.2f * v;
        m = fmaxf(m, v);
    }
    outH[(size_t)bn * 512 + outOff + o] = m;
}

__global__ void diag_kernel(const float* __restrict__ G, float* __restrict__ sq)
{
    int bn = blockIdx.x * blockDim.x + threadIdx.x;
    if (bn < BB * NN) {
        int b = bn >> 11, n = bn & 2047;
        sq[bn] = G[((size_t)b * NN + n) * NN + n];
    }
}

// ---------------- kNN select core (cached per-thread argmax) ----------------
#define KNN_SELECT_BODY(dist, out, bn)                                           \
    {                                                                            \
        float bv = -FLT_MAX; int bi = 0x7fffffff;                                \
        _Pragma("unroll")                                                        \
        for (int u = 0; u < NN / 256; u++) {                                     \
            int j = u * 256 + tid;                                               \
            float v = dist[j];                                                   \
            if (v > bv) { bv = v; bi = j; }                                      \
        }                                                                        \
        for (int sel = 0; sel < KK; sel++) {                                     \
            float cv = bv; int ci = bi;                                          \
            _Pragma("unroll")                                                    \
            for (int off = 16; off > 0; off >>= 1) {                             \
                float ov = __shfl_down_sync(0xffffffffu, cv, off);               \
                int oi = __shfl_down_sync(0xffffffffu, ci, off);                 \
                if (ov > cv || (ov == cv && oi < ci)) { cv = ov; ci = oi; }      \
            }                                                                    \
            if (lane == 0) { wv[warp] = cv; wi[warp] = ci; }                     \
            __syncthreads();                                                     \
            if (tid == 0) {                                                      \
                float fv = wv[0]; int fi = wi[0];                                \
                _Pragma("unroll")                                                \
                for (int w = 1; w < 8; w++)                                      \
                    if (wv[w] > fv || (wv[w] == fv && wi[w] < fi)) {             \
                        fv = wv[w]; fi = wi[w];                                  \
                    }                                                            \
                out[(bn) * KK + sel] = fi;                                       \
                sfi = fi;                                                        \
            }                                                                    \
            __syncthreads();                                                     \
            int fi = sfi;                                                        \
            if ((fi & 255) == tid) {                                             \
                dist[fi] = -FLT_MAX;                                             \
                bv = -FLT_MAX; bi = 0x7fffffff;                                  \
                _Pragma("unroll")                                                \
                for (int u = 0; u < NN / 256; u++) {                             \
                    int j = u * 256 + tid;                                       \
                    float v = dist[j];                                           \
                    if (v > bv) { bv = v; bi = j; }                              \
                }                                                                \
            }                                                                    \
        }                                                                        \
    }

// layers 2-4: distances from gram matrix
__global__ void knn_select(const float* __restrict__ G, const float* __restrict__ sq,
                           int* __restrict__ out)
{
    int bn = blockIdx.x;
    int b = bn >> 11, n = bn & 2047;
    __shared__ float dist[NN];
    __shared__ float wv[8];
    __shared__ int wi[8];
    __shared__ int sfi;
    int tid = threadIdx.x;
    int lane = tid & 31, warp = tid >> 5;
    const float* row = G + ((size_t)b * NN + n) * NN;
    const float* sqb = sq + (b << 11);
    float sqn = sqb[n];
    for (int j = tid; j < NN; j += 256)
        dist[j] = 2.f * row[j] - sqn - sqb[j];
    __syncthreads();
    KNN_SELECT_BODY(dist, out, bn)
}

// layer 1: distances from xyz with the EXACT gram-path numerics:
// inner = ((0 + x*x) + y*y) + z*z  via explicit fma chain (ascending c order),
// dist = 2*inner - sq[n] - sq[j]  — identical expression to knn_select.
__global__ void knn_xyz(const float* __restrict__ x, int* __restrict__ out)
{
    int bn = blockIdx.x;
    int b = bn >> 11, n = bn & 2047;
    __shared__ float dist[NN];
    __shared__ float sx[NN], sy[NN], sz[NN], ssq[NN];
    __shared__ float wv[8];
    __shared__ int wi[8];
    __shared__ int sfi;
    int tid = threadIdx.x;
    int lane = tid & 31, warp = tid >> 5;
    const float* xb = x + (size_t)(b << 11) * 3;
    for (int j = tid; j < NN; j += 256) {
        float xv = xb[j * 3 + 0], yv = xb[j * 3 + 1], zv = xb[j * 3 + 2];
        sx[j] = xv; sy[j] = yv; sz[j] = zv;
        float s = 0.f;
        s = __fmaf_rn(xv, xv, s);
        s = __fmaf_rn(yv, yv, s);
        s = __fmaf_rn(zv, zv, s);
        ssq[j] = s;
    }
    __syncthreads();
    float xi = sx[n], yi = sy[n], zi = sz[n];
    float sqn = ssq[n];
    for (int j = tid; j < NN; j += 256) {
        float s = 0.f;
        s = __fmaf_rn(xi, sx[j], s);
        s = __fmaf_rn(yi, sy[j], s);
        s = __fmaf_rn(zi, sz[j], s);
        dist[j] = 2.f * s - sqn - ssq[j];
    }
    __syncthreads();
    KNN_SELECT_BODY(dist, out, bn)
}

// ---------------- conv5 BN partials ----------------
__global__ void bn5_partial(const float* __restrict__ y5, float* __restrict__ psum,
                            float* __restrict__ psq)
{
    int blk = blockIdx.x;
    int t0 = blk * 256;
    int tid = threadIdx.x;
    float s[4] = {0, 0, 0, 0}, s2[4] = {0, 0, 0, 0};
    for (int t = t0; t < t0 + 256; t++) {
        const float* row = y5 + (size_t)t * DD;
#pragma unroll
        for (int i = 0; i < 4; i++) {
            float v = row[tid + i * 256];
            s[i] += v; s2[i] += v * v;
        }
    }
#pragma unroll
    for (int i = 0; i < 4; i++) {
        psum[(size_t)blk * DD + tid + i * 256] = s[i];
        psq[(size_t)blk * DD + tid + i * 256] = s2[i];
    }
}

// ---------------- BN5 + leaky + patch max-pool + cls ----------------
__global__ void pool_kernel(const float* __restrict__ y5, const float* __restrict__ mean,
                            const float* __restrict__ rstd, const float* __restrict__ g5,
                            const float* __restrict__ b5, const float* __restrict__ cls,
                            float* __restrict__ t)
{
    int tok = blockIdx.x;
    int b = tok / 65, l = tok - b * 65;
    int tid = threadIdx.x;
    if (l == 0) {
        for (int d = tid; d < DD; d += 256) t[(size_t)tok * DD + d] = cls[d];
    } else {
        int p = l - 1;
        int base = b * NN + p * PS;
        for (int d = tid; d < DD; d += 256) {
            float mu = mean[d], rs = rstd[d], gg = g5[d], bb = b5[d];
            float m = -FLT_MAX;
            for (int s = 0; s < PS; s++) {
                float v = y5[(size_t)(base + s) * DD + d];
                v = (v - mu) * rs * gg + bb;
                v = (v >= 0.f) ? v : 0.2f * v;
                m = fmaxf(m, v);
            }
            t[(size_t)tok * DD + d] = m;
        }
    }
}

// ---------------- LayerNorm (optional fused pos-add) ----------------
__global__ void ln_kernel(float* __restrict__ t, const float* __restrict__ pos,
                          const float* __restrict__ g, const float* __restrict__ b,
                          float* __restrict__ out)
{
    int tok = blockIdx.x, tid = threadIdx.x;
    __shared__ float rs1[256], rs2[256];
    float* trow = t + (size_t)tok * DD;
    float loc[4];
    float s = 0.f, s2 = 0.f;
#pragma unroll
    for (int i = 0; i < 4; i++) {
        int d = tid + i * 256;
        float v = trow[d];
        if (pos) { v += pos[(size_t)tok * DD + d]; trow[d] = v; }
        loc[i] = v; s += v; s2 += v * v;
    }
    rs1[tid] = s; rs2[tid] = s2;
    __syncthreads();
    for (int st = 128; st > 0; st >>= 1) {
        if (tid < st) { rs1[tid] += rs1[tid + st]; rs2[tid] += rs2[tid + st]; }
        __syncthreads();
    }
    float mean = rs1[0] * (1.f / DD);
    float var = rs2[0] * (1.f / DD) - mean * mean;
    float rstd = rsqrtf(var + 1e-5f);
#pragma unroll
    for (int i = 0; i < 4; i++) {
        int d = tid + i * 256;
        out[(size_t)tok * DD + d] = (loc[i] - mean) * rstd * g[d] + b[d];
    }
}

// ---------------- attention ----------------
__global__ void attn_kernel(const float* __restrict__ qkv, float* __restrict__ z)
{
    int l = blockIdx.x, hh = blockIdx.y, b = blockIdx.z;
    int tid = threadIdx.x;   // 128
    __shared__ float sq_[64];
    __shared__ float sc[65];
    __shared__ float sinv;
    const float* qrow = qkv + (size_t)(b * 65 + l) * 1536 + hh * 64;
    if (tid < 64) sq_[tid] = qrow[tid];
    __syncthreads();
    if (tid < 65) {
        const float* krow = qkv + (size_t)(b * 65 + tid) * 1536 + 512 + hh * 64;
        float s = 0.f;
#pragma unroll 16
        for (int d = 0; d < 64; d++) s += sq_[d] * krow[d];
        sc[tid] = s * 0.125f;
    }
    __syncthreads();
    if (tid == 0) {
        float mx = -FLT_MAX;
        for (int m = 0; m < 65; m++) mx = fmaxf(mx, sc[m]);
        float sum = 0.f;
        for (int m = 0; m < 65; m++) { float e = expf(sc[m] - mx); sc[m] = e; sum += e; }
        sinv = 1.f / sum;
    }
    __syncthreads();
    if (tid < 64) {
        float inv = sinv;
        float acc = 0.f;
        for (int m = 0; m < 65; m++) {
            const float* vrow = qkv + (size_t)(b * 65 + m) * 1536 + 1024 + hh * 64;
            acc += sc[m] * vrow[tid];
        }
        z[(size_t)(b * 65 + l) * INNER + hh * 64 + tid] = acc * inv;
    }
}

__global__ void out_copy(const float* __restrict__ t, float* __restrict__ out)
{
    int i = blockIdx.x * blockDim.x + threadIdx.x;
    if (i < BB * PP * DD) {
        int d = i & (DD - 1);
        int bp = i >> 10;
        int b = bp >> 6, p = bp & 63;
        out[i] = t[((size_t)(b * 65 + 1 + p) << 10) + d];
    }
}

// ---------------- host driver ----------------
static void edge_layer(const float* featPtr, int lda, int C,
                       const float* w, const float* g, const float* b,
                       int O, int outOff, bool first, const float* xyz,
                       float* h, float* G, float* sq, int* knn, float* ey,
                       float* psum, float* psq, float* mean, float* rstd)
{
    if (first) {
        knn_xyz<<<BB * NN, 256>>>(xyz, knn);
    } else {
        dim3 gg(NN / 128, NN / 128, BB);
        gemm128<true, 0, false><<<gg, 256>>>(
            featPtr, lda, (size_t)NN * lda, featPtr, lda, (size_t)NN * lda,
            nullptr, G, NN, (size_t)NN * NN, NN, NN, C);
        diag_kernel<<<(BB * NN + 255) / 256, 256>>>(G, sq);
        knn_select<<<BB * NN, 256>>>(G, sq, knn);
    }
    int bnv = (O == 64) ? 64 : 128;
    if (O == 64) {
        dim3 ge(1, RBLK);
        ec_gemm<64><<<ge, 256>>>(featPtr, lda, C, knn, w, O, ey, psum, psq);
    } else {
        dim3 ge(O / 128, RBLK);
        ec_gemm<128><<<ge, 256>>>(featPtr, lda, C, knn, w, O, ey, psum, psq);
    }
    bn_reduce2<<<(O + 255) / 256, 256>>>(psum, psq, RBLK, O, bnv,
                                         1.f / (float)EROWS, mean, rstd);
    ec_apply_y<<<BB * NN, O>>>(ey, O, mean, rstd, g, b, h, outOff);
}

extern "C" void kernel_launch(void* const* d_in, const int* in_sizes, int n_in,
                              void* d_out, int out_size)
{
    const float* x      = (const float*)d_in[0];
    const float* pos    = (const float*)d_in[1];
    const float* w1 = (const float*)d_in[2];  const float* g1 = (const float*)d_in[3];  const float* b1 = (const float*)d_in[4];
    const float* w2 = (const float*)d_in[5];  const float* g2 = (const float*)d_in[6];  const float* b2 = (const float*)d_in[7];
    const float* w3 = (const float*)d_in[8];  const float* g3 = (const float*)d_in[9];  const float* b3 = (const float*)d_in[10];
    const float* w4 = (const float*)d_in[11]; const float* g4 = (const float*)d_in[12]; const float* b4 = (const float*)d_in[13];
    const float* w5 = (const float*)d_in[14]; const float* g5 = (const float*)d_in[15]; const float* b5 = (const float*)d_in[16];
    const float* cls    = (const float*)d_in[17];
    const float* ln1g   = (const float*)d_in[18];
    const float* ln1b   = (const float*)d_in[19];
    const float* wqkv   = (const float*)d_in[20];
    const float* wout   = (const float*)d_in[21];
    const float* bout   = (const float*)d_in[22];
    const float* ln2g   = (const float*)d_in[23];
    const float* ln2b   = (const float*)d_in[24];
    const float* wff1   = (const float*)d_in[25];
    const float* bff1   = (const float*)d_in[26];
    const float* wff2   = (const float*)d_in[27];
    const float* bff2   = (const float*)d_in[28];
    float* out = (float*)d_out;

    float *h, *G, *sq, *ey, *psum, *psq, *mean, *rstd, *y5, *t, *ln, *qkv, *z, *ff;
    int* knn;
    cudaGetSymbolAddress((void**)&h, g_h);
    cudaGetSymbolAddress((void**)&G, g_G);
    cudaGetSymbolAddress((void**)&sq, g_sq);
    cudaGetSymbolAddress((void**)&knn, g_knn);
    cudaGetSymbolAddress((void**)&ey, g_ey);
    cudaGetSymbolAddress((void**)&psum, g_psum);
    cudaGetSymbolAddress((void**)&psq, g_psq);
    cudaGetSymbolAddress((void**)&mean, g_mean);
    cudaGetSymbolAddress((void**)&rstd, g_rstd);
    cudaGetSymbolAddress((void**)&y5, g_y5);
    cudaGetSymbolAddress((void**)&t, g_t);
    cudaGetSymbolAddress((void**)&ln, g_ln);
    cudaGetSymbolAddress((void**)&qkv, g_qkv);
    cudaGetSymbolAddress((void**)&z, g_z);
    cudaGetSymbolAddress((void**)&ff, g_ff);

    // ---- DGCNN backbone ----
    edge_layer(x,       3,   3,   w1, g1, b1, 64,  0,   true,  x,
               h, G, sq, knn, ey, psum, psq, mean, rstd);
    edge_layer(h + 0,   512, 64,  w2, g2, b2, 64,  64,  false, nullptr,
               h, G, sq, knn, ey, psum, psq, mean, rstd);
    edge_layer(h + 64,  512, 64,  w3, g3, b3, 128, 128, false, nullptr,
               h, G, sq, knn, ey, psum, psq, mean, rstd);
    edge_layer(h + 128, 512, 128, w4, g4, b4, 256, 256, false, nullptr,
               h, G, sq, knn, ey, psum, psq, mean, rstd);

    // ---- conv5 ----
    {
        dim3 gg(DD / 128, BB * NN / 128);
        gemm128<true, 0, false><<<gg, 256>>>(
            h, 512, 0, w5, 512, 0, nullptr, y5, DD, 0, BB * NN, DD, 512);
        bn5_partial<<<BB * NN / 256, 256>>>(y5, psum, psq);
        bn_reduce2<<<(DD + 255) / 256, 256>>>(psum, psq, BB * NN / 256, DD, DD,
                                              1.f / (8.f * 2048.f), mean, rstd);
        pool_kernel<<<TOK, 256>>>(y5, mean, rstd, g5, b5, cls, t);
    }

    // ---- transformer ----
    for (int i = 0; i < 6; i++) {
        const float* wqkv_i = wqkv + (size_t)i * DD * 3 * INNER;
        const float* wout_i = wout + (size_t)i * INNER * DD;
        const float* bout_i = bout + (size_t)i * DD;
        const float* wff1_i = wff1 + (size_t)i * DD * MLPD;
        const float* bff1_i = bff1 + (size_t)i * MLPD;
        const float* wff2_i = wff2 + (size_t)i * MLPD * DD;
        const float* bff2_i = bff2 + (size_t)i * DD;

        ln_kernel<<<TOK, 256>>>(t, pos, ln1g + i * DD, ln1b + i * DD, ln);

        dim3 gq(3 * INNER / 64, (TOK + 63) / 64);
        gemm64<0, false><<<gq, 256>>>(ln, DD, wqkv_i, 3 * INNER, nullptr,
                                      qkv, 3 * INNER, TOK, 3 * INNER, DD);

        attn_kernel<<<dim3(65, 8, BB), 128>>>(qkv, z);

        dim3 gp(DD / 64, (TOK + 63) / 64);
        gemm64<0, true><<<gp, 256>>>(z, INNER, wout_i, DD, bout_i,
                                     t, DD, TOK, DD, INNER);

        ln_kernel<<<TOK, 256>>>(t, nullptr, ln2g + i * DD, ln2b + i * DD, ln);

        dim3 gf1(MLPD / 64, (TOK + 63) / 64);
        gemm64<1, false><<<gf1, 256>>>(ln, DD, wff1_i, MLPD, bff1_i,
                                       ff, MLPD, TOK, MLPD, DD);

        dim3 gf2(DD / 64, (TOK + 63) / 64);
        gemm64<0, true><<<gf2, 256>>>(ff, MLPD, wff2_i, DD, bff2_i,
                                      t, DD, TOK, DD, MLPD);
    }

    out_copy<<<(BB * PP * DD + 255) / 256, 256>>>(t, out);
}

// round 11
// speedup vs baseline: 1.0357x; 1.0357x over previous
#include <cuda_runtime.h>
#include <cuda_bf16.h>
#include <cfloat>
#include <math.h>

// ---------------- problem constants ----------------
#define BB 8
#define NN 2048
#define KK 20
#define PP 64
#define PS 32
#define DD 1024
#define TOK (BB * (PP + 1))   // 520
#define INNER 512
#define MLPD 2048
#define EROWS (BB * NN * KK)  // 327680
#define RBLK (EROWS / 128)    // 2560

// ---------------- scratch ----------------
__device__ float g_h[BB * NN * 512];
__device__ float g_G[BB * NN * NN];
__device__ float g_sq[BB * NN];
__device__ int   g_knn[EROWS];
__device__ float g_ey[(size_t)EROWS * 256];
__device__ float g_psum[RBLK * 256];
__device__ float g_psq[RBLK * 256];
__device__ float g_mean[1024];
__device__ float g_rstd[1024];
__device__ float g_y5[BB * NN * DD];
__device__ float g_t[TOK * DD];
__device__ float g_ln[TOK * DD];
__device__ float g_qkv[TOK * 3 * INNER];
__device__ float g_z[TOK * INNER];
__device__ float g_ff[TOK * MLPD];

__device__ __forceinline__ float4 ld4(const float* p) { return *(const float4*)p; }

// ---------------- tf32 helpers ----------------
__device__ __forceinline__ unsigned f2tf(float f) {
    unsigned u;
    asm("cvt.rna.tf32.f32 %0, %1;" : "=r"(u) : "f"(f));
    return u;
}
__device__ __forceinline__ void mma8(float (&c)[4], const unsigned (&a)[4], const unsigned (&b)[2]) {
    asm volatile("mma.sync.aligned.m16n8k8.row.col.f32.tf32.tf32.f32 "
                 "{%0,%1,%2,%3}, {%4,%5,%6,%7}, {%8,%9}, {%0,%1,%2,%3};"
                 : "+f"(c[0]), "+f"(c[1]), "+f"(c[2]), "+f"(c[3])
                 : "r"(a[0]), "r"(a[1]), "r"(a[2]), "r"(a[3]),
                   "r"(b[0]), "r"(b[1]));
}

// ================= double-buffered 128x128x16 SGEMM (gram / conv5) =================
template <bool TRANSB, int ACT, bool ADDC>
__global__ __launch_bounds__(256, 2)
void gemm128(const float* __restrict__ A, int lda, size_t strideA,
             const float* __restrict__ Bm, int ldb, size_t strideB,
             const float* __restrict__ bias,
             float* __restrict__ C, int ldc, size_t strideC,
             int M, int N, int K)
{
    const int BK = 16;
    __shared__ float As[2][BK][128];
    __shared__ float Bs[2][BK][128];
    A  += (size_t)blockIdx.z * strideA;
    Bm += (size_t)blockIdx.z * strideB;
    C  += (size_t)blockIdx.z * strideC;
    int bm = blockIdx.y * 128, bn = blockIdx.x * 128;
    int tid = threadIdx.x;
    int trow = tid >> 4, tcol = tid & 15;

    float4 ra[2], rb[2];

    auto loadA = [&](int k0) {
#pragma unroll
        for (int i = 0; i < 2; i++) {
            int row = i * 64 + (tid >> 2), q = tid & 3;
            int gm = bm + row, gk = k0 + q * 4;
            if (k0 + BK <= K) {
                ra[i] = (gm < M) ? ld4(&A[(size_t)gm * lda + gk]) : make_float4(0, 0, 0, 0);
            } else {
                float v[4];
#pragma unroll
                for (int j = 0; j < 4; j++)
                    v[j] = (gm < M && gk + j < K) ? A[(size_t)gm * lda + gk + j] : 0.f;
                ra[i] = make_float4(v[0], v[1], v[2], v[3]);
            }
        }
    };
    auto loadB = [&](int k0) {
#pragma unroll
        for (int i = 0; i < 2; i++) {
            if (TRANSB) {
                int row = i * 64 + (tid >> 2), q = tid & 3;
                int gn = bn + row, gk = k0 + q * 4;
                if (k0 + BK <= K) {
                    rb[i] = (gn < N) ? ld4(&Bm[(size_t)gn * ldb + gk]) : make_float4(0, 0, 0, 0);
                } else {
                    float v[4];
#pragma unroll
                    for (int j = 0; j < 4; j++)
                        v[j] = (gn < N && gk + j < K) ? Bm[(size_t)gn * ldb + gk + j] : 0.f;
                    rb[i] = make_float4(v[0], v[1], v[2], v[3]);
                }
            } else {
                int krow = i * 8 + (tid >> 5), nq = tid & 31;
                int gk = k0 + krow, gn = bn + nq * 4;
                if (gk < K && gn < N) rb[i] = ld4(&Bm[(size_t)gk * ldb + gn]);
                else rb[i] = make_float4(0, 0, 0, 0);
            }
        }
    };
    auto storeA = [&](int p) {
#pragma unroll
        for (int i = 0; i < 2; i++) {
            int row = i * 64 + (tid >> 2), q = tid & 3;
            As[p][q * 4 + 0][row] = ra[i].x;
            As[p][q * 4 + 1][row] = ra[i].y;
            As[p][q * 4 + 2][row] = ra[i].z;
            As[p][q * 4 + 3][row] = ra[i].w;
        }
    };
    auto storeB = [&](int p) {
#pragma unroll
        for (int i = 0; i < 2; i++) {
            if (TRANSB) {
                int row = i * 64 + (tid >> 2), q = tid & 3;
                Bs[p][q * 4 + 0][row] = rb[i].x;
                Bs[p][q * 4 + 1][row] = rb[i].y;
                Bs[p][q * 4 + 2][row] = rb[i].z;
                Bs[p][q * 4 + 3][row] = rb[i].w;
            } else {
                int krow = i * 8 + (tid >> 5), nq = tid & 31;
                *(float4*)&Bs[p][krow][nq * 4] = rb[i];
            }
        }
    };

    float acc[8][8];
#pragma unroll
    for (int i = 0; i < 8; i++)
#pragma unroll
        for (int j = 0; j < 8; j++) acc[i][j] = 0.f;

    int nk = (K + BK - 1) / BK;
    loadA(0); loadB(0);
    storeA(0); storeB(0);
    __syncthreads();
    int p = 0;
    for (int it = 0; it < nk; it++) {
        if (it + 1 < nk) { loadA((it + 1) * BK); loadB((it + 1) * BK); }
#pragma unroll
        for (int k = 0; k < BK; k++) {
            float4 a0 = ld4(&As[p][k][trow * 8]);
            float4 a1 = ld4(&As[p][k][trow * 8 + 4]);
            float4 b0 = ld4(&Bs[p][k][tcol * 8]);
            float4 b1 = ld4(&Bs[p][k][tcol * 8 + 4]);
            float a[8] = {a0.x, a0.y, a0.z, a0.w, a1.x, a1.y, a1.z, a1.w};
            float b[8] = {b0.x, b0.y, b0.z, b0.w, b1.x, b1.y, b1.z, b1.w};
#pragma unroll
            for (int i = 0; i < 8; i++)
#pragma unroll
                for (int j = 0; j < 8; j++) acc[i][j] += a[i] * b[j];
        }
        if (it + 1 < nk) { storeA(p ^ 1); storeB(p ^ 1); }
        __syncthreads();
        p ^= 1;
    }
#pragma unroll
    for (int i = 0; i < 8; i++) {
        int gm = bm + trow * 8 + i;
        if (gm >= M) continue;
#pragma unroll
        for (int j = 0; j < 8; j++) {
            int gn = bn + tcol * 8 + j;
            if (gn >= N) continue;
            float v = acc[i][j];
            if (bias) v += bias[gn];
            if (ACT == 1) v = 0.5f * v * (1.f + erff(v * 0.70710678118654752f));
            size_t off = (size_t)gm * ldc + gn;
            if (ADDC) v += C[off];
            C[off] = v;
        }
    }
}

// ================= double-buffered 64x64x32 SGEMM (transformer, B=[K,N]) =================
template <int ACT, bool ADDC>
__global__ __launch_bounds__(256)
void gemm64(const float* __restrict__ A, int lda,
            const float* __restrict__ Bm, int ldb,
            const float* __restrict__ bias,
            float* __restrict__ C, int ldc,
            int M, int N, int K)
{
    const int BK = 32;
    __shared__ float As[2][BK][64];
    __shared__ float Bs[2][BK][64];
    int bm = blockIdx.y * 64, bn = blockIdx.x * 64;
    int tid = threadIdx.x;
    int trow = tid >> 4, tcol = tid & 15;
    float4 ra[2], rb[2];

    auto loadA = [&](int k0) {
        int row = tid >> 2, q = tid & 3;
        int gm = bm + row, gk = k0 + q * 8;
        if (gm < M) {
            ra[0] = ld4(&A[(size_t)gm * lda + gk]);
            ra[1] = ld4(&A[(size_t)gm * lda + gk + 4]);
        } else {
            ra[0] = make_float4(0, 0, 0, 0);
            ra[1] = make_float4(0, 0, 0, 0);
        }
    };
    auto loadB = [&](int k0) {
        int krow = tid >> 3, gn = bn + (tid & 7) * 8;
        int gk = k0 + krow;
        rb[0] = ld4(&Bm[(size_t)gk * ldb + gn]);
        rb[1] = ld4(&Bm[(size_t)gk * ldb + gn + 4]);
    };
    auto storeA = [&](int p) {
        int row = tid >> 2, q = tid & 3;
#pragma unroll
        for (int i = 0; i < 2; i++) {
            As[p][q * 8 + i * 4 + 0][row] = (i ? ra[1].x : ra[0].x);
            As[p][q * 8 + i * 4 + 1][row] = (i ? ra[1].y : ra[0].y);
            As[p][q * 8 + i * 4 + 2][row] = (i ? ra[1].z : ra[0].z);
            As[p][q * 8 + i * 4 + 3][row] = (i ? ra[1].w : ra[0].w);
        }
    };
    auto storeB = [&](int p) {
        int krow = tid >> 3, nq = (tid & 7) * 8;
        *(float4*)&Bs[p][krow][nq] = rb[0];
        *(float4*)&Bs[p][krow][nq + 4] = rb[1];
    };

    float acc[4][4];
#pragma unroll
    for (int i = 0; i < 4; i++)
#pragma unroll
        for (int j = 0; j < 4; j++) acc[i][j] = 0.f;

    int nk = K / BK;
    loadA(0); loadB(0);
    storeA(0); storeB(0);
    __syncthreads();
    int p = 0;
    for (int it = 0; it < nk; it++) {
        if (it + 1 < nk) { loadA((it + 1) * BK); loadB((it + 1) * BK); }
#pragma unroll
        for (int k = 0; k < BK; k++) {
            float4 a4 = ld4(&As[p][k][trow * 4]);
            float4 b4 = ld4(&Bs[p][k][tcol * 4]);
            float a[4] = {a4.x, a4.y, a4.z, a4.w};
            float b[4] = {b4.x, b4.y, b4.z, b4.w};
#pragma unroll
            for (int i = 0; i < 4; i++)
#pragma unroll
                for (int j = 0; j < 4; j++) acc[i][j] += a[i] * b[j];
        }
        if (it + 1 < nk) { storeA(p ^ 1); storeB(p ^ 1); }
        __syncthreads();
        p ^= 1;
    }
#pragma unroll
    for (int i = 0; i < 4; i++) {
        int gm = bm + trow * 4 + i;
        if (gm >= M) continue;
#pragma unroll
        for (int j = 0; j < 4; j++) {
            int gn = bn + tcol * 4 + j;
            float v = acc[i][j];
            if (bias) v += bias[gn];
            if (ACT == 1) v = 0.5f * v * (1.f + erff(v * 0.70710678118654752f));
            size_t off = (size_t)gm * ldc + gn;
            if (ADDC) v += C[off];
            C[off] = v;
        }
    }
}

// ================= fp32 gather-fused EdgeConv GEMM (layer 1 only, K=6) =================
template <int BN>
__global__ __launch_bounds__(256, 2)
void ec_gemm(const float* __restrict__ feat, int stride, int C,
             const int* __restrict__ knn,
             const float* __restrict__ w, int O,
             float* __restrict__ y,
             float* __restrict__ psum, float* __restrict__ psq)
{
    const int BK = 16;
    constexpr int TN = BN / 16;
    __shared__ float As[2][BK][128];
    __shared__ float Bs[2][BK][BN];
    __shared__ float red[16][BN];
    __shared__ int s_nbr[128], s_ctr[128];
    int tid = threadIdx.x;
    int bm = blockIdx.y * 128, bn0 = blockIdx.x * BN;
    int C2 = 2 * C;
    for (int i = tid; i < 128; i += 256) {
        int r = bm + i;
        int pnt = r / KK;
        int b = pnt >> 11;
        int j = knn[r];
        s_nbr[i] = ((b << 11) + j) * stride;
        s_ctr[i] = pnt * stride;
    }
    __syncthreads();
    int trow = tid >> 4, tcol = tid & 15;
    bool c4ok = ((C & 3) == 0);

    float4 ra[2], rb[BN / 64];

    auto loadA = [&](int k0) {
#pragma unroll
        for (int i = 0; i < 2; i++) {
            int row = i * 64 + (tid >> 2), q = tid & 3;
            int c4 = k0 + q * 4;
            if (k0 + BK <= C2 && c4ok) {
                if (c4 + 4 <= C) {
                    float4 nb = ld4(&feat[s_nbr[row] + c4]);
                    float4 ct = ld4(&feat[s_ctr[row] + c4]);
                    ra[i] = make_float4(nb.x - ct.x, nb.y - ct.y, nb.z - ct.z, nb.w - ct.w);
                } else {
                    ra[i] = ld4(&feat[s_ctr[row] + c4 - C]);
                }
            } else {
                float v[4];
#pragma unroll
                for (int j = 0; j < 4; j++) {
                    int c = c4 + j;
                    float xv = 0.f;
                    if (c < C2) {
                        if (c < C) xv = feat[s_nbr[row] + c] - feat[s_ctr[row] + c];
                        else       xv = feat[s_ctr[row] + c - C];
                    }
                    v[j] = xv;
                }
                ra[i] = make_float4(v[0], v[1], v[2], v[3]);
            }
        }
    };
    auto loadB = [&](int k0) {
#pragma unroll
        for (int i = 0; i < BN / 64; i++) {
            int row = i * 64 + (tid >> 2), q = tid & 3;
            int gn = bn0 + row, gk = k0 + q * 4;
            if (k0 + BK <= C2 && c4ok) {
                rb[i] = (gn < O) ? ld4(&w[(size_t)gn * C2 + gk]) : make_float4(0, 0, 0, 0);
            } else {
                float v[4];
#pragma unroll
                for (int j = 0; j < 4; j++)
                    v[j] = (gn < O && gk + j < C2) ? w[(size_t)gn * C2 + gk + j] : 0.f;
                rb[i] = make_float4(v[0], v[1], v[2], v[3]);
            }
        }
    };
    auto storeA = [&](int p) {
#pragma unroll
        for (int i = 0; i < 2; i++) {
            int row = i * 64 + (tid >> 2), q = tid & 3;
            As[p][q * 4 + 0][row] = ra[i].x;
            As[p][q * 4 + 1][row] = ra[i].y;
            As[p][q * 4 + 2][row] = ra[i].z;
            As[p][q * 4 + 3][row] = ra[i].w;
        }
    };
    auto storeB = [&](int p) {
#pragma unroll
        for (int i = 0; i < BN / 64; i++) {
            int row = i * 64 + (tid >> 2), q = tid & 3;
            Bs[p][q * 4 + 0][row] = rb[i].x;
            Bs[p][q * 4 + 1][row] = rb[i].y;
            Bs[p][q * 4 + 2][row] = rb[i].z;
            Bs[p][q * 4 + 3][row] = rb[i].w;
        }
    };

    float acc[8][TN];
#pragma unroll
    for (int i = 0; i < 8; i++)
#pragma unroll
        for (int j = 0; j < TN; j++) acc[i][j] = 0.f;

    int nk = (C2 + BK - 1) / BK;
    loadA(0); loadB(0);
    storeA(0); storeB(0);
    __syncthreads();
    int p = 0;
    for (int it = 0; it < nk; it++) {
        if (it + 1 < nk) { loadA((it + 1) * BK); loadB((it + 1) * BK); }
#pragma unroll
        for (int k = 0; k < BK; k++) {
            float a[8], b[TN];
            float4 a0 = ld4(&As[p][k][trow * 8]);
            float4 a1 = ld4(&As[p][k][trow * 8 + 4]);
            a[0] = a0.x; a[1] = a0.y; a[2] = a0.z; a[3] = a0.w;
            a[4] = a1.x; a[5] = a1.y; a[6] = a1.z; a[7] = a1.w;
#pragma unroll
            for (int j = 0; j < TN / 4; j++) {
                float4 b4 = ld4(&Bs[p][k][tcol * TN + j * 4]);
                b[j * 4 + 0] = b4.x; b[j * 4 + 1] = b4.y;
                b[j * 4 + 2] = b4.z; b[j * 4 + 3] = b4.w;
            }
#pragma unroll
            for (int i = 0; i < 8; i++)
#pragma unroll
                for (int j = 0; j < TN; j++) acc[i][j] += a[i] * b[j];
        }
        if (it + 1 < nk) { storeA(p ^ 1); storeB(p ^ 1); }
        __syncthreads();
        p ^= 1;
    }
#pragma unroll
    for (int i = 0; i < 8; i++) {
        int m = bm + trow * 8 + i;
#pragma unroll
        for (int j = 0; j < TN; j++) {
            int col = bn0 + tcol * TN + j;
            y[(size_t)m * O + col] = acc[i][j];
        }
    }
    float cs[TN], cq[TN];
#pragma unroll
    for (int j = 0; j < TN; j++) {
        float s = 0.f, s2 = 0.f;
#pragma unroll
        for (int i = 0; i < 8; i++) { s += acc[i][j]; s2 += acc[i][j] * acc[i][j]; }
        cs[j] = s; cq[j] = s2;
    }
    size_t pbase = ((size_t)blockIdx.x * gridDim.y + blockIdx.y) * BN;
#pragma unroll
    for (int j = 0; j < TN; j++) red[trow][tcol * TN + j] = cs[j];
    __syncthreads();
    if (tid < BN) {
        float s = 0.f;
#pragma unroll
        for (int r = 0; r < 16; r++) s += red[r][tid];
        psum[pbase + tid] = s;
    }
    __syncthreads();
#pragma unroll
    for (int j = 0; j < TN; j++) red[trow][tcol * TN + j] = cq[j];
    __syncthreads();
    if (tid < BN) {
        float s = 0.f;
#pragma unroll
        for (int r = 0; r < 16; r++) s += red[r][tid];
        psq[pbase + tid] = s;
    }
}

// ================= tf32x3 tensor-core EdgeConv GEMM (layers 2-4) =================
// y[r][o] = f(r,:) . w[o,:] via mma.sync m16n8k8 tf32 with hi/lo split (fp32-quality).
// Block: 128 rows x BN cols, 8 warps (warp tile 32 x BN/2). Fused deterministic BN partials.
template <int BN>
__global__ __launch_bounds__(256)
void ec_gemm_tc(const float* __restrict__ feat, int stride, int C,
                const int* __restrict__ knn,
                const float* __restrict__ w, int O,
                float* __restrict__ y,
                float* __restrict__ psum, float* __restrict__ psq)
{
    constexpr int BK = 32;
    constexpr int AP = 132;        // padded row stride (banks)
    constexpr int BP = BN + 4;
    constexpr int NT = BN / 16;    // n8 tiles per warp
    extern __shared__ unsigned smbuf[];
    unsigned* Ah = smbuf;
    unsigned* Al = Ah + BK * AP;
    unsigned* Bh = Al + BK * AP;
    unsigned* Bl = Bh + BK * BP;
    float* redS = (float*)(Bl + BK * BP);
    float* redQ = redS + 4 * BN;
    int* s_nbr = (int*)(redQ + 4 * BN);
    int* s_ctr = s_nbr + 128;

    int tid = threadIdx.x;
    int lane = tid & 31, warp = tid >> 5;
    int wm = warp >> 1, wn = warp & 1;
    int g = lane >> 2, t = lane & 3;
    int bm = blockIdx.y * 128, bn0 = blockIdx.x * BN;
    int C2 = 2 * C;

    for (int i = tid; i < 128; i += 256) {
        int r = bm + i;
        int pnt = r / KK;
        int b = pnt >> 11;
        s_nbr[i] = ((b << 11) + knn[r]) * stride;
        s_ctr[i] = pnt * stride;
    }

    float acc[2][NT][4];
#pragma unroll
    for (int i = 0; i < 2; i++)
#pragma unroll
        for (int j = 0; j < NT; j++)
#pragma unroll
            for (int c = 0; c < 4; c++) acc[i][j][c] = 0.f;

    int arow = tid >> 3;        // 0..31
    int aq = (tid & 7) * 4;     // 0,4,...,28

    for (int k0 = 0; k0 < C2; k0 += BK) {
        __syncthreads();
        // A tile: 128 rows x 32 k, gathered edge features, converted to hi/lo tf32
#pragma unroll
        for (int i = 0; i < 4; i++) {
            int row = i * 32 + arow;
            int c4 = k0 + aq;
            float4 v;
            if (c4 + 4 <= C) {
                float4 nb = ld4(&feat[s_nbr[row] + c4]);
                float4 ct = ld4(&feat[s_ctr[row] + c4]);
                v = make_float4(nb.x - ct.x, nb.y - ct.y, nb.z - ct.z, nb.w - ct.w);
            } else {
                v = ld4(&feat[s_ctr[row] + c4 - C]);
            }
            float vv[4] = {v.x, v.y, v.z, v.w};
#pragma unroll
            for (int j = 0; j < 4; j++) {
                unsigned hi = f2tf(vv[j]);
                float lo = vv[j] - __uint_as_float(hi);
                Ah[(aq + j) * AP + row] = hi;
                Al[(aq + j) * AP + row] = f2tf(lo);
            }
        }
        // B tile: BN rows (output channels) x 32 k from w[n][k]
#pragma unroll
        for (int i = 0; i < BN / 32; i++) {
            int n = i * 32 + arow;
            float4 v = ld4(&w[(size_t)(bn0 + n) * C2 + k0 + aq]);
            float vv[4] = {v.x, v.y, v.z, v.w};
#pragma unroll
            for (int j = 0; j < 4; j++) {
                unsigned hi = f2tf(vv[j]);
                float lo = vv[j] - __uint_as_float(hi);
                Bh[(aq + j) * BP + n] = hi;
                Bl[(aq + j) * BP + n] = f2tf(lo);
            }
        }
        __syncthreads();
#pragma unroll
        for (int ks = 0; ks < 4; ks++) {
            int kb = ks * 8;
            unsigned ah[2][4], al[2][4];
#pragma unroll
            for (int i = 0; i < 2; i++) {
                int m0 = wm * 32 + i * 16;
                ah[i][0] = Ah[(kb + t) * AP + m0 + g];
                ah[i][1] = Ah[(kb + t) * AP + m0 + g + 8];
                ah[i][2] = Ah[(kb + t + 4) * AP + m0 + g];
                ah[i][3] = Ah[(kb + t + 4) * AP + m0 + g + 8];
                al[i][0] = Al[(kb + t) * AP + m0 + g];
                al[i][1] = Al[(kb + t) * AP + m0 + g + 8];
                al[i][2] = Al[(kb + t + 4) * AP + m0 + g];
                al[i][3] = Al[(kb + t + 4) * AP + m0 + g + 8];
            }
#pragma unroll
            for (int j = 0; j < NT; j++) {
                int n0 = wn * (BN / 2) + j * 8;
                unsigned bh[2], bl[2];
                bh[0] = Bh[(kb + t) * BP + n0 + g];
                bh[1] = Bh[(kb + t + 4) * BP + n0 + g];
                bl[0] = Bl[(kb + t) * BP + n0 + g];
                bl[1] = Bl[(kb + t + 4) * BP + n0 + g];
#pragma unroll
                for (int i = 0; i < 2; i++) {
                    mma8(acc[i][j], ah[i], bh);
                    mma8(acc[i][j], ah[i], bl);
                    mma8(acc[i][j], al[i], bh);
                }
            }
        }
    }
    // ---- write y (float2 stores; cols 2t,2t+1 adjacent) ----
#pragma unroll
    for (int i = 0; i < 2; i++) {
        int row = bm + wm * 32 + i * 16 + g;
#pragma unroll
        for (int j = 0; j < NT; j++) {
            int col = bn0 + wn * (BN / 2) + j * 8 + 2 * t;
            *(float2*)&y[(size_t)row * O + col] = make_float2(acc[i][j][0], acc[i][j][1]);
            *(float2*)&y[(size_t)(row + 8) * O + col] = make_float2(acc[i][j][2], acc[i][j][3]);
        }
    }
    // ---- deterministic BN partials: per-column sum / sumsq over 128 rows ----
#pragma unroll
    for (int j = 0; j < NT; j++) {
        float se = acc[0][j][0] + acc[0][j][2] + acc[1][j][0] + acc[1][j][2];
        float so = acc[0][j][1] + acc[0][j][3] + acc[1][j][1] + acc[1][j][3];
        float qe = acc[0][j][0] * acc[0][j][0] + acc[0][j][2] * acc[0][j][2]
                 + acc[1][j][0] * acc[1][j][0] + acc[1][j][2] * acc[1][j][2];
        float qo = acc[0][j][1] * acc[0][j][1] + acc[0][j][3] * acc[0][j][3]
                 + acc[1][j][1] * acc[1][j][1] + acc[1][j][3] * acc[1][j][3];
#pragma unroll
        for (int m = 4; m <= 16; m <<= 1) {
            se += __shfl_xor_sync(0xffffffffu, se, m);
            so += __shfl_xor_sync(0xffffffffu, so, m);
            qe += __shfl_xor_sync(0xffffffffu, qe, m);
            qo += __shfl_xor_sync(0xffffffffu, qo, m);
        }
        if (g == 0) {
            int col = wn * (BN / 2) + j * 8 + 2 * t;
            redS[wm * BN + col] = se; redS[wm * BN + col + 1] = so;
            redQ[wm * BN + col] = qe; redQ[wm * BN + col + 1] = qo;
        }
    }
    __syncthreads();
    if (tid < BN) {
        float s = redS[tid] + redS[BN + tid] + redS[2 * BN + tid] + redS[3 * BN + tid];
        float q = redQ[tid] + redQ[BN + tid] + redQ[2 * BN + tid] + redQ[3 * BN + tid];
        size_t pbase = ((size_t)blockIdx.x * gridDim.y + blockIdx.y) * BN;
        psum[pbase + tid] = s;
        psq[pbase + tid] = q;
    }
}

// ---------------- deterministic BN finalize (strided partial layout) ----------------
__global__ void bn_reduce2(const float* __restrict__ psum, const float* __restrict__ psq,
                           int npart, int O, int bnsz, float cnt_inv,
                           float* __restrict__ mean, float* __restrict__ rstd)
{
    int o = blockIdx.x * blockDim.x + threadIdx.x;
    if (o >= O) return;
    int colblk = o / bnsz, c = o % bnsz;
    const float* ps = psum + (size_t)colblk * npart * bnsz + c;
    const float* pq = psq + (size_t)colblk * npart * bnsz + c;
    float s = 0.f, s2 = 0.f;
    for (int i = 0; i < npart; i++) {
        s  += ps[(size_t)i * bnsz];
        s2 += pq[(size_t)i * bnsz];
    }
    float mu = s * cnt_inv;
    float var = s2 * cnt_inv - mu * mu;
    mean[o] = mu;
    rstd[o] = rsqrtf(var + 1e-5f);
}

// ---------------- BN + lrelu + max over k ----------------
__global__ void ec_apply_y(const float* __restrict__ y, int O,
                           const float* __restrict__ mean, const float* __restrict__ rstd,
                           const float* __restrict__ gam, const float* __restrict__ bet,
                           float* __restrict__ outH, int outOff)
{
    int bn = blockIdx.x;
    int o = threadIdx.x;
    float mu = mean[o], rs = rstd[o], gg = gam[o], bb = bet[o];
    float m = -FLT_MAX;
    for (int kk = 0; kk < KK; kk++) {
        float v = y[((size_t)bn * KK + kk) * O + o];
        v = (v - mu) * rs * gg + bb;
        v = (v >= 0.f) ? v : 0.2f * v;
        m = fmaxf(m, v);
    }
    outH[(size_t)bn * 512 + outOff + o] = m;
}

__global__ void diag_kernel(const float* __restrict__ G, float* __restrict__ sq)
{
    int bn = blockIdx.x * blockDim.x + threadIdx.x;
    if (bn < BB * NN) {
        int b = bn >> 11, n = bn & 2047;
        sq[bn] = G[((size_t)b * NN + n) * NN + n];
    }
}

// ---------------- kNN select core (cached per-thread argmax) ----------------
#define KNN_SELECT_BODY(dist, out, bn)                                           \
    {                                                                            \
        float bv = -FLT_MAX; int bi = 0x7fffffff;                                \
        _Pragma("unroll")                                                        \
        for (int u = 0; u < NN / 256; u++) {                                     \
            int j = u * 256 + tid;                                               \
            float v = dist[j];                                                   \
            if (v > bv) { bv = v; bi = j; }                                      \
        }                                                                        \
        for (int sel = 0; sel < KK; sel++) {                                     \
            float cv = bv; int ci = bi;                                          \
            _Pragma("unroll")                                                    \
            for (int off = 16; off > 0; off >>= 1) {                             \
                float ov = __shfl_down_sync(0xffffffffu, cv, off);               \
                int oi = __shfl_down_sync(0xffffffffu, ci, off);                 \
                if (ov > cv || (ov == cv && oi < ci)) { cv = ov; ci = oi; }      \
            }                                                                    \
            if (lane == 0) { wv[warp] = cv; wi[warp] = ci; }                     \
            __syncthreads();                                                     \
            if (tid == 0) {                                                      \
                float fv = wv[0]; int fi = wi[0];                                \
                _Pragma("unroll")                                                \
                for (int w = 1; w < 8; w++)                                      \
                    if (wv[w] > fv || (wv[w] == fv && wi[w] < fi)) {             \
                        fv = wv[w]; fi = wi[w];                                  \
                    }                                                            \
                out[(bn) * KK + sel] = fi;                                       \
                sfi = fi;                                                        \
            }                                                                    \
            __syncthreads();                                                     \
            int fi = sfi;                                                        \
            if ((fi & 255) == tid) {                                             \
                dist[fi] = -FLT_MAX;                                             \
                bv = -FLT_MAX; bi = 0x7fffffff;                                  \
                _Pragma("unroll")                                                \
                for (int u = 0; u < NN / 256; u++) {                             \
                    int j = u * 256 + tid;                                       \
                    float v = dist[j];                                           \
                    if (v > bv) { bv = v; bi = j; }                              \
                }                                                                \
            }                                                                    \
        }                                                                        \
    }

// layers 2-4: distances from gram matrix
__global__ void knn_select(const float* __restrict__ G, const float* __restrict__ sq,
                           int* __restrict__ out)
{
    int bn = blockIdx.x;
    int b = bn >> 11, n = bn & 2047;
    __shared__ float dist[NN];
    __shared__ float wv[8];
    __shared__ int wi[8];
    __shared__ int sfi;
    int tid = threadIdx.x;
    int lane = tid & 31, warp = tid >> 5;
    const float* row = G + ((size_t)b * NN + n) * NN;
    const float* sqb = sq + (b << 11);
    float sqn = sqb[n];
    for (int j = tid; j < NN; j += 256)
        dist[j] = 2.f * row[j] - sqn - sqb[j];
    __syncthreads();
    KNN_SELECT_BODY(dist, out, bn)
}

// layer 1: distances from xyz with exact gram-path numerics (fma chain, same expr)
__global__ void knn_xyz(const float* __restrict__ x, int* __restrict__ out)
{
    int bn = blockIdx.x;
    int b = bn >> 11, n = bn & 2047;
    __shared__ float dist[NN];
    __shared__ float sx[NN], sy[NN], sz[NN], ssq[NN];
    __shared__ float wv[8];
    __shared__ int wi[8];
    __shared__ int sfi;
    int tid = threadIdx.x;
    int lane = tid & 31, warp = tid >> 5;
    const float* xb = x + (size_t)(b << 11) * 3;
    for (int j = tid; j < NN; j += 256) {
        float xv = xb[j * 3 + 0], yv = xb[j * 3 + 1], zv = xb[j * 3 + 2];
        sx[j] = xv; sy[j] = yv; sz[j] = zv;
        float s = 0.f;
        s = __fmaf_rn(xv, xv, s);
        s = __fmaf_rn(yv, yv, s);
        s = __fmaf_rn(zv, zv, s);
        ssq[j] = s;
    }
    __syncthreads();
    float xi = sx[n], yi = sy[n], zi = sz[n];
    float sqn = ssq[n];
    for (int j = tid; j < NN; j += 256) {
        float s = 0.f;
        s = __fmaf_rn(xi, sx[j], s);
        s = __fmaf_rn(yi, sy[j], s);
        s = __fmaf_rn(zi, sz[j], s);
        dist[j] = 2.f * s - sqn - ssq[j];
    }
    __syncthreads();
    KNN_SELECT_BODY(dist, out, bn)
}

// ---------------- conv5 BN partials ----------------
__global__ void bn5_partial(const float* __restrict__ y5, float* __restrict__ psum,
                            float* __restrict__ psq)
{
    int blk = blockIdx.x;
    int t0 = blk * 256;
    int tid = threadIdx.x;
    float s[4] = {0, 0, 0, 0}, s2[4] = {0, 0, 0, 0};
    for (int t = t0; t < t0 + 256; t++) {
        const float* row = y5 + (size_t)t * DD;
#pragma unroll
        for (int i = 0; i < 4; i++) {
            float v = row[tid + i * 256];
            s[i] += v; s2[i] += v * v;
        }
    }
#pragma unroll
    for (int i = 0; i < 4; i++) {
        psum[(size_t)blk * DD + tid + i * 256] = s[i];
        psq[(size_t)blk * DD + tid + i * 256] = s2[i];
    }
}

// ---------------- BN5 + leaky + patch max-pool + cls ----------------
__global__ void pool_kernel(const float* __restrict__ y5, const float* __restrict__ mean,
                            const float* __restrict__ rstd, const float* __restrict__ g5,
                            const float* __restrict__ b5, const float* __restrict__ cls,
                            float* __restrict__ t)
{
    int tok = blockIdx.x;
    int b = tok / 65, l = tok - b * 65;
    int tid = threadIdx.x;
    if (l == 0) {
        for (int d = tid; d < DD; d += 256) t[(size_t)tok * DD + d] = cls[d];
    } else {
        int p = l - 1;
        int base = b * NN + p * PS;
        for (int d = tid; d < DD; d += 256) {
            float mu = mean[d], rs = rstd[d], gg = g5[d], bb = b5[d];
            float m = -FLT_MAX;
            for (int s = 0; s < PS; s++) {
                float v = y5[(size_t)(base + s) * DD + d];
                v = (v - mu) * rs * gg + bb;
                v = (v >= 0.f) ? v : 0.2f * v;
                m = fmaxf(m, v);
            }
            t[(size_t)tok * DD + d] = m;
        }
    }
}

// ---------------- LayerNorm (optional fused pos-add) ----------------
__global__ void ln_kernel(float* __restrict__ t, const float* __restrict__ pos,
                          const float* __restrict__ g, const float* __restrict__ b,
                          float* __restrict__ out)
{
    int tok = blockIdx.x, tid = threadIdx.x;
    __shared__ float rs1[256], rs2[256];
    float* trow = t + (size_t)tok * DD;
    float loc[4];
    float s = 0.f, s2 = 0.f;
#pragma unroll
    for (int i = 0; i < 4; i++) {
        int d = tid + i * 256;
        float v = trow[d];
        if (pos) { v += pos[(size_t)tok * DD + d]; trow[d] = v; }
        loc[i] = v; s += v; s2 += v * v;
    }
    rs1[tid] = s; rs2[tid] = s2;
    __syncthreads();
    for (int st = 128; st > 0; st >>= 1) {
        if (tid < st) { rs1[tid] += rs1[tid + st]; rs2[tid] += rs2[tid + st]; }
        __syncthreads();
    }
    float mean = rs1[0] * (1.f / DD);
    float var = rs2[0] * (1.f / DD) - mean * mean;
    float rstd = rsqrtf(var + 1e-5f);
#pragma unroll
    for (int i = 0; i < 4; i++) {
        int d = tid + i * 256;
        out[(size_t)tok * DD + d] = (loc[i] - mean) * rstd * g[d] + b[d];
    }
}

// ---------------- attention ----------------
__global__ void attn_kernel(const float* __restrict__ qkv, float* __restrict__ z)
{
    int l = blockIdx.x, hh = blockIdx.y, b = blockIdx.z;
    int tid = threadIdx.x;   // 128
    __shared__ float sq_[64];
    __shared__ float sc[65];
    __shared__ float sinv;
    const float* qrow = qkv + (size_t)(b * 65 + l) * 1536 + hh * 64;
    if (tid < 64) sq_[tid] = qrow[tid];
    __syncthreads();
    if (tid < 65) {
        const float* krow = qkv + (size_t)(b * 65 + tid) * 1536 + 512 + hh * 64;
        float s = 0.f;
#pragma unroll 16
        for (int d = 0; d < 64; d++) s += sq_[d] * krow[d];
        sc[tid] = s * 0.125f;
    }
    __syncthreads();
    if (tid == 0) {
        float mx = -FLT_MAX;
        for (int m = 0; m < 65; m++) mx = fmaxf(mx, sc[m]);
        float sum = 0.f;
        for (int m = 0; m < 65; m++) { float e = expf(sc[m] - mx); sc[m] = e; sum += e; }
        sinv = 1.f / sum;
    }
    __syncthreads();
    if (tid < 64) {
        float inv = sinv;
        float acc = 0.f;
        for (int m = 0; m < 65; m++) {
            const float* vrow = qkv + (size_t)(b * 65 + m) * 1536 + 1024 + hh * 64;
            acc += sc[m] * vrow[tid];
        }
        z[(size_t)(b * 65 + l) * INNER + hh * 64 + tid] = acc * inv;
    }
}

__global__ void out_copy(const float* __restrict__ t, float* __restrict__ out)
{
    int i = blockIdx.x * blockDim.x + threadIdx.x;
    if (i < BB * PP * DD) {
        int d = i & (DD - 1);
        int bp = i >> 10;
        int b = bp >> 6, p = bp & 63;
        out[i] = t[((size_t)(b * 65 + 1 + p) << 10) + d];
    }
}

// ---------------- host driver ----------------
static size_t tc_smem_bytes(int BN)
{
    int BP = BN + 4;
    size_t words = 2 * 32 * 132 + 2 * 32 * (size_t)BP + 8 * (size_t)BN + 256;
    return words * 4;
}

static void edge_layer(const float* featPtr, int lda, int C,
                       const float* w, const float* g, const float* b,
                       int O, int outOff, bool first, const float* xyz,
                       float* h, float* G, float* sq, int* knn, float* ey,
                       float* psum, float* psq, float* mean, float* rstd)
{
    if (first) {
        knn_xyz<<<BB * NN, 256>>>(xyz, knn);
    } else {
        dim3 gg(NN / 128, NN / 128, BB);
        gemm128<true, 0, false><<<gg, 256>>>(
            featPtr, lda, (size_t)NN * lda, featPtr, lda, (size_t)NN * lda,
            nullptr, G, NN, (size_t)NN * NN, NN, NN, C);
        diag_kernel<<<(BB * NN + 255) / 256, 256>>>(G, sq);
        knn_select<<<BB * NN, 256>>>(G, sq, knn);
    }
    int bnv;
    if (first) {
        bnv = 64;
        dim3 ge(1, RBLK);
        ec_gemm<64><<<ge, 256>>>(featPtr, lda, C, knn, w, O, ey, psum, psq);
    } else if (O == 64) {
        bnv = 64;
        dim3 ge(1, RBLK);
        ec_gemm_tc<64><<<ge, 256, tc_smem_bytes(64)>>>(featPtr, lda, C, knn, w, O,
                                                       ey, psum, psq);
    } else {
        bnv = 128;
        dim3 ge(O / 128, RBLK);
        ec_gemm_tc<128><<<ge, 256, tc_smem_bytes(128)>>>(featPtr, lda, C, knn, w, O,
                                                         ey, psum, psq);
    }
    bn_reduce2<<<(O + 255) / 256, 256>>>(psum, psq, RBLK, O, bnv,
                                         1.f / (float)EROWS, mean, rstd);
    ec_apply_y<<<BB * NN, O>>>(ey, O, mean, rstd, g, b, h, outOff);
}

extern "C" void kernel_launch(void* const* d_in, const int* in_sizes, int n_in,
                              void* d_out, int out_size)
{
    const float* x      = (const float*)d_in[0];
    const float* pos    = (const float*)d_in[1];
    const float* w1 = (const float*)d_in[2];  const float* g1 = (const float*)d_in[3];  const float* b1 = (const float*)d_in[4];
    const float* w2 = (const float*)d_in[5];  const float* g2 = (const float*)d_in[6];  const float* b2 = (const float*)d_in[7];
    const float* w3 = (const float*)d_in[8];  const float* g3 = (const float*)d_in[9];  const float* b3 = (const float*)d_in[10];
    const float* w4 = (const float*)d_in[11]; const float* g4 = (const float*)d_in[12]; const float* b4 = (const float*)d_in[13];
    const float* w5 = (const float*)d_in[14]; const float* g5 = (const float*)d_in[15]; const float* b5 = (const float*)d_in[16];
    const float* cls    = (const float*)d_in[17];
    const float* ln1g   = (const float*)d_in[18];
    const float* ln1b   = (const float*)d_in[19];
    const float* wqkv   = (const float*)d_in[20];
    const float* wout   = (const float*)d_in[21];
    const float* bout   = (const float*)d_in[22];
    const float* ln2g   = (const float*)d_in[23];
    const float* ln2b   = (const float*)d_in[24];
    const float* wff1   = (const float*)d_in[25];
    const float* bff1   = (const float*)d_in[26];
    const float* wff2   = (const float*)d_in[27];
    const float* bff2   = (const float*)d_in[28];
    float* out = (float*)d_out;

    // allow >48KB dynamic smem for the tc kernels (attribute set; not an allocation)
    cudaFuncSetAttribute(ec_gemm_tc<64>, cudaFuncAttributeMaxDynamicSharedMemorySize,
                         (int)tc_smem_bytes(64));
    cudaFuncSetAttribute(ec_gemm_tc<128>, cudaFuncAttributeMaxDynamicSharedMemorySize,
                         (int)tc_smem_bytes(128));

    float *h, *G, *sq, *ey, *psum, *psq, *mean, *rstd, *y5, *t, *ln, *qkv, *z, *ff;
    int* knn;
    cudaGetSymbolAddress((void**)&h, g_h);
    cudaGetSymbolAddress((void**)&G, g_G);
    cudaGetSymbolAddress((void**)&sq, g_sq);
    cudaGetSymbolAddress((void**)&knn, g_knn);
    cudaGetSymbolAddress((void**)&ey, g_ey);
    cudaGetSymbolAddress((void**)&psum, g_psum);
    cudaGetSymbolAddress((void**)&psq, g_psq);
    cudaGetSymbolAddress((void**)&mean, g_mean);
    cudaGetSymbolAddress((void**)&rstd, g_rstd);
    cudaGetSymbolAddress((void**)&y5, g_y5);
    cudaGetSymbolAddress((void**)&t, g_t);
    cudaGetSymbolAddress((void**)&ln, g_ln);
    cudaGetSymbolAddress((void**)&qkv, g_qkv);
    cudaGetSymbolAddress((void**)&z, g_z);
    cudaGetSymbolAddress((void**)&ff, g_ff);

    // ---- DGCNN backbone ----
    edge_layer(x,       3,   3,   w1, g1, b1, 64,  0,   true,  x,
               h, G, sq, knn, ey, psum, psq, mean, rstd);
    edge_layer(h + 0,   512, 64,  w2, g2, b2, 64,  64,  false, nullptr,
               h, G, sq, knn, ey, psum, psq, mean, rstd);
    edge_layer(h + 64,  512, 64,  w3, g3, b3, 128, 128, false, nullptr,
               h, G, sq, knn, ey, psum, psq, mean, rstd);
    edge_layer(h + 128, 512, 128, w4, g4, b4, 256, 256, false, nullptr,
               h, G, sq, knn, ey, psum, psq, mean, rstd);

    // ---- conv5 ----
    {
        dim3 gg(DD / 128, BB * NN / 128);
        gemm128<true, 0, false><<<gg, 256>>>(
            h, 512, 0, w5, 512, 0, nullptr, y5, DD, 0, BB * NN, DD, 512);
        bn5_partial<<<BB * NN / 256, 256>>>(y5, psum, psq);
        bn_reduce2<<<(DD + 255) / 256, 256>>>(psum, psq, BB * NN / 256, DD, DD,
                                              1.f / (8.f * 2048.f), mean, rstd);
        pool_kernel<<<TOK, 256>>>(y5, mean, rstd, g5, b5, cls, t);
    }

    // ---- transformer ----
    for (int i = 0; i < 6; i++) {
        const float* wqkv_i = wqkv + (size_t)i * DD * 3 * INNER;
        const float* wout_i = wout + (size_t)i * INNER * DD;
        const float* bout_i = bout + (size_t)i * DD;
        const float* wff1_i = wff1 + (size_t)i * DD * MLPD;
        const float* bff1_i = bff1 + (size_t)i * MLPD;
        const float* wff2_i = wff2 + (size_t)i * MLPD * DD;
        const float* bff2_i = bff2 + (size_t)i * DD;

        ln_kernel<<<TOK, 256>>>(t, pos, ln1g + i * DD, ln1b + i * DD, ln);

        dim3 gq(3 * INNER / 64, (TOK + 63) / 64);
        gemm64<0, false><<<gq, 256>>>(ln, DD, wqkv_i, 3 * INNER, nullptr,
                                      qkv, 3 * INNER, TOK, 3 * INNER, DD);

        attn_kernel<<<dim3(65, 8, BB), 128>>>(qkv, z);

        dim3 gp(DD / 64, (TOK + 63) / 64);
        gemm64<0, true><<<gp, 256>>>(z, INNER, wout_i, DD, bout_i,
                                     t, DD, TOK, DD, INNER);

        ln_kernel<<<TOK, 256>>>(t, nullptr, ln2g + i * DD, ln2b + i * DD, ln);

        dim3 gf1(MLPD / 64, (TOK + 63) / 64);
        gemm64<1, false><<<gf1, 256>>>(ln, DD, wff1_i, MLPD, bff1_i,
                                       ff, MLPD, TOK, MLPD, DD);

        dim3 gf2(DD / 64, (TOK + 63) / 64);
        gemm64<0, true><<<gf2, 256>>>(ff, MLPD, wff2_i, DD, bff2_i,
                                      t, DD, TOK, DD, MLPD);
    }

    out_copy<<<(BB * PP * DD + 255) / 256, 256>>>(t, out);
}

// round 12
// speedup vs baseline: 1.4626x; 1.4122x over previous
#include <cuda_runtime.h>
#include <cuda_bf16.h>
#include <cfloat>
#include <math.h>

// ---------------- problem constants ----------------
#define BB 8
#define NN 2048
#define KK 20
#define PP 64
#define PS 32
#define DD 1024
#define TOK (BB * (PP + 1))   // 520
#define INNER 512
#define MLPD 2048
#define EROWS (BB * NN * KK)  // 327680
#define NPTS (BB * NN)        // 16384

// ---------------- scratch ----------------
__device__ float g_h[NPTS * 512];
__device__ float g_G[BB * NN * NN];
__device__ float g_sq[NPTS];
__device__ int   g_knn[EROWS];
__device__ float g_u[NPTS * 256];
__device__ float g_t2[NPTS * 256];
__device__ float g_umax[NPTS * 256];
__device__ float g_umin[NPTS * 256];
__device__ float g_psum[512 * 1024];
__device__ float g_psq[512 * 1024];
__device__ float g_mean[1024];
__device__ float g_rstd[1024];
__device__ float g_y5[NPTS * DD];
__device__ float g_t[TOK * DD];
__device__ float g_ln[TOK * DD];
__device__ float g_qkv[TOK * 3 * INNER];
__device__ float g_z[TOK * INNER];
__device__ float g_ff[TOK * MLPD];

__device__ __forceinline__ float4 ld4(const float* p) { return *(const float4*)p; }

// ================= double-buffered 128x128x16 SGEMM (gram / conv5 / uv) =================
template <bool TRANSB, int ACT, bool ADDC>
__global__ __launch_bounds__(256, 2)
void gemm128(const float* __restrict__ A, int lda, size_t strideA,
             const float* __restrict__ Bm, int ldb, size_t strideB,
             const float* __restrict__ bias,
             float* __restrict__ C, int ldc, size_t strideC,
             int M, int N, int K)
{
    const int BK = 16;
    __shared__ float As[2][BK][128];
    __shared__ float Bs[2][BK][128];
    A  += (size_t)blockIdx.z * strideA;
    Bm += (size_t)blockIdx.z * strideB;
    C  += (size_t)blockIdx.z * strideC;
    int bm = blockIdx.y * 128, bn = blockIdx.x * 128;
    int tid = threadIdx.x;
    int trow = tid >> 4, tcol = tid & 15;

    float4 ra[2], rb[2];

    auto loadA = [&](int k0) {
#pragma unroll
        for (int i = 0; i < 2; i++) {
            int row = i * 64 + (tid >> 2), q = tid & 3;
            int gm = bm + row, gk = k0 + q * 4;
            if (k0 + BK <= K) {
                ra[i] = (gm < M) ? ld4(&A[(size_t)gm * lda + gk]) : make_float4(0, 0, 0, 0);
            } else {
                float v[4];
#pragma unroll
                for (int j = 0; j < 4; j++)
                    v[j] = (gm < M && gk + j < K) ? A[(size_t)gm * lda + gk + j] : 0.f;
                ra[i] = make_float4(v[0], v[1], v[2], v[3]);
            }
        }
    };
    auto loadB = [&](int k0) {
#pragma unroll
        for (int i = 0; i < 2; i++) {
            if (TRANSB) {
                int row = i * 64 + (tid >> 2), q = tid & 3;
                int gn = bn + row, gk = k0 + q * 4;
                if (k0 + BK <= K) {
                    rb[i] = (gn < N) ? ld4(&Bm[(size_t)gn * ldb + gk]) : make_float4(0, 0, 0, 0);
                } else {
                    float v[4];
#pragma unroll
                    for (int j = 0; j < 4; j++)
                        v[j] = (gn < N && gk + j < K) ? Bm[(size_t)gn * ldb + gk + j] : 0.f;
                    rb[i] = make_float4(v[0], v[1], v[2], v[3]);
                }
            } else {
                int krow = i * 8 + (tid >> 5), nq = tid & 31;
                int gk = k0 + krow, gn = bn + nq * 4;
                if (gk < K && gn < N) rb[i] = ld4(&Bm[(size_t)gk * ldb + gn]);
                else rb[i] = make_float4(0, 0, 0, 0);
            }
        }
    };
    auto storeA = [&](int p) {
#pragma unroll
        for (int i = 0; i < 2; i++) {
            int row = i * 64 + (tid >> 2), q = tid & 3;
            As[p][q * 4 + 0][row] = ra[i].x;
            As[p][q * 4 + 1][row] = ra[i].y;
            As[p][q * 4 + 2][row] = ra[i].z;
            As[p][q * 4 + 3][row] = ra[i].w;
        }
    };
    auto storeB = [&](int p) {
#pragma unroll
        for (int i = 0; i < 2; i++) {
            if (TRANSB) {
                int row = i * 64 + (tid >> 2), q = tid & 3;
                Bs[p][q * 4 + 0][row] = rb[i].x;
                Bs[p][q * 4 + 1][row] = rb[i].y;
                Bs[p][q * 4 + 2][row] = rb[i].z;
                Bs[p][q * 4 + 3][row] = rb[i].w;
            } else {
                int krow = i * 8 + (tid >> 5), nq = tid & 31;
                *(float4*)&Bs[p][krow][nq * 4] = rb[i];
            }
        }
    };

    float acc[8][8];
#pragma unroll
    for (int i = 0; i < 8; i++)
#pragma unroll
        for (int j = 0; j < 8; j++) acc[i][j] = 0.f;

    int nk = (K + BK - 1) / BK;
    loadA(0); loadB(0);
    storeA(0); storeB(0);
    __syncthreads();
    int p = 0;
    for (int it = 0; it < nk; it++) {
        if (it + 1 < nk) { loadA((it + 1) * BK); loadB((it + 1) * BK); }
#pragma unroll
        for (int k = 0; k < BK; k++) {
            float4 a0 = ld4(&As[p][k][trow * 8]);
            float4 a1 = ld4(&As[p][k][trow * 8 + 4]);
            float4 b0 = ld4(&Bs[p][k][tcol * 8]);
            float4 b1 = ld4(&Bs[p][k][tcol * 8 + 4]);
            float a[8] = {a0.x, a0.y, a0.z, a0.w, a1.x, a1.y, a1.z, a1.w};
            float b[8] = {b0.x, b0.y, b0.z, b0.w, b1.x, b1.y, b1.z, b1.w};
#pragma unroll
            for (int i = 0; i < 8; i++)
#pragma unroll
                for (int j = 0; j < 8; j++) acc[i][j] += a[i] * b[j];
        }
        if (it + 1 < nk) { storeA(p ^ 1); storeB(p ^ 1); }
        __syncthreads();
        p ^= 1;
    }
#pragma unroll
    for (int i = 0; i < 8; i++) {
        int gm = bm + trow * 8 + i;
        if (gm >= M) continue;
#pragma unroll
        for (int j = 0; j < 8; j++) {
            int gn = bn + tcol * 8 + j;
            if (gn >= N) continue;
            float v = acc[i][j];
            if (bias) v += bias[gn];
            if (ACT == 1) v = 0.5f * v * (1.f + erff(v * 0.70710678118654752f));
            size_t off = (size_t)gm * ldc + gn;
            if (ADDC) v += C[off];
            C[off] = v;
        }
    }
}

// ================= double-buffered 64x64x32 SGEMM (transformer, B=[K,N]) =================
template <int ACT, bool ADDC>
__global__ __launch_bounds__(256)
void gemm64(const float* __restrict__ A, int lda,
            const float* __restrict__ Bm, int ldb,
            const float* __restrict__ bias,
            float* __restrict__ C, int ldc,
            int M, int N, int K)
{
    const int BK = 32;
    __shared__ float As[2][BK][64];
    __shared__ float Bs[2][BK][64];
    int bm = blockIdx.y * 64, bn = blockIdx.x * 64;
    int tid = threadIdx.x;
    int trow = tid >> 4, tcol = tid & 15;
    float4 ra[2], rb[2];

    auto loadA = [&](int k0) {
        int row = tid >> 2, q = tid & 3;
        int gm = bm + row, gk = k0 + q * 8;
        if (gm < M) {
            ra[0] = ld4(&A[(size_t)gm * lda + gk]);
            ra[1] = ld4(&A[(size_t)gm * lda + gk + 4]);
        } else {
            ra[0] = make_float4(0, 0, 0, 0);
            ra[1] = make_float4(0, 0, 0, 0);
        }
    };
    auto loadB = [&](int k0) {
        int krow = tid >> 3, gn = bn + (tid & 7) * 8;
        int gk = k0 + krow;
        rb[0] = ld4(&Bm[(size_t)gk * ldb + gn]);
        rb[1] = ld4(&Bm[(size_t)gk * ldb + gn + 4]);
    };
    auto storeA = [&](int p) {
        int row = tid >> 2, q = tid & 3;
#pragma unroll
        for (int i = 0; i < 2; i++) {
            As[p][q * 8 + i * 4 + 0][row] = (i ? ra[1].x : ra[0].x);
            As[p][q * 8 + i * 4 + 1][row] = (i ? ra[1].y : ra[0].y);
            As[p][q * 8 + i * 4 + 2][row] = (i ? ra[1].z : ra[0].z);
            As[p][q * 8 + i * 4 + 3][row] = (i ? ra[1].w : ra[0].w);
        }
    };
    auto storeB = [&](int p) {
        int krow = tid >> 3, nq = (tid & 7) * 8;
        *(float4*)&Bs[p][krow][nq] = rb[0];
        *(float4*)&Bs[p][krow][nq + 4] = rb[1];
    };

    float acc[4][4];
#pragma unroll
    for (int i = 0; i < 4; i++)
#pragma unroll
        for (int j = 0; j < 4; j++) acc[i][j] = 0.f;

    int nk = K / BK;
    loadA(0); loadB(0);
    storeA(0); storeB(0);
    __syncthreads();
    int p = 0;
    for (int it = 0; it < nk; it++) {
        if (it + 1 < nk) { loadA((it + 1) * BK); loadB((it + 1) * BK); }
#pragma unroll
        for (int k = 0; k < BK; k++) {
            float4 a4 = ld4(&As[p][k][trow * 4]);
            float4 b4 = ld4(&Bs[p][k][tcol * 4]);
            float a[4] = {a4.x, a4.y, a4.z, a4.w};
            float b[4] = {b4.x, b4.y, b4.z, b4.w};
#pragma unroll
            for (int i = 0; i < 4; i++)
#pragma unroll
                for (int j = 0; j < 4; j++) acc[i][j] += a[i] * b[j];
        }
        if (it + 1 < nk) { storeA(p ^ 1); storeB(p ^ 1); }
        __syncthreads();
        p ^= 1;
    }
#pragma unroll
    for (int i = 0; i < 4; i++) {
        int gm = bm + trow * 4 + i;
        if (gm >= M) continue;
#pragma unroll
        for (int j = 0; j < 4; j++) {
            int gn = bn + tcol * 4 + j;
            float v = acc[i][j];
            if (bias) v += bias[gn];
            if (ACT == 1) v = 0.5f * v * (1.f + erff(v * 0.70710678118654752f));
            size_t off = (size_t)gm * ldc + gn;
            if (ADDC) v += C[off];
            C[off] = v;
        }
    }
}

// ================= EdgeConv via per-point factorization =================
// y[edge r=(p,k)][o] = u[nbr][o] + v[p][o],  u = feat.w[:, :C], v = t2 - u, t2 = feat.w[:, C:]
// Single gather pass: BN partial sums + per-point max/min of u[nbr].
__global__ void ec_uv_stats(const float* __restrict__ u, const float* __restrict__ t2,
                            const int* __restrict__ knn, int O,
                            float* __restrict__ umax, float* __restrict__ umin,
                            float* __restrict__ psum, float* __restrict__ psq)
{
    __shared__ int sk[32 * KK];
    int blk = blockIdx.x;        // 512 blocks x 32 points
    int o = threadIdx.x;         // O threads
    int base = blk * 32;
    for (int i = o; i < 32 * KK; i += blockDim.x) {
        int p = base + i / KK;
        sk[i] = ((p >> 11) << 11) + knn[(size_t)base * KK + i];
    }
    __syncthreads();
    float S = 0.f, Q = 0.f;
    for (int pi = 0; pi < 32; pi++) {
        int p = base + pi;
        size_t po = (size_t)p * O + o;
        float up = u[po];
        float v = t2[po] - up;
        float mx = -FLT_MAX, mn = FLT_MAX;
#pragma unroll
        for (int k = 0; k < KK; k++) {
            float uu = u[(size_t)sk[pi * KK + k] * O + o];
            mx = fmaxf(mx, uu);
            mn = fminf(mn, uu);
            float y = uu + v;
            S += y;
            Q += y * y;
        }
        umax[po] = mx;
        umin[po] = mn;
    }
    psum[(size_t)blk * O + o] = S;
    psq[(size_t)blk * O + o] = Q;
}

// Dense apply: BN affine (alpha,beta) + lrelu of extremal u + v. No gather.
__global__ void ec_apply_uv(const float* __restrict__ u, const float* __restrict__ t2,
                            const float* __restrict__ umax, const float* __restrict__ umin,
                            const float* __restrict__ mean, const float* __restrict__ rstd,
                            const float* __restrict__ gam, const float* __restrict__ bet,
                            float* __restrict__ outH, int outOff, int O)
{
    int idx = blockIdx.x * blockDim.x + threadIdx.x;   // NPTS*O
    int p = idx / O, o = idx - p * O;
    float al = gam[o] * rstd[o];
    float be = bet[o] - mean[o] * al;
    float v = t2[idx] - u[idx];
    float m = (al >= 0.f) ? umax[idx] : umin[idx];
    float val = al * (m + v) + be;
    val = (val >= 0.f) ? val : 0.2f * val;
    outH[(size_t)p * 512 + outOff + o] = val;
}

// ---------------- deterministic BN finalize (strided partial layout) ----------------
__global__ void bn_reduce2(const float* __restrict__ psum, const float* __restrict__ psq,
                           int npart, int O, int bnsz, float cnt_inv,
                           float* __restrict__ mean, float* __restrict__ rstd)
{
    int o = blockIdx.x * blockDim.x + threadIdx.x;
    if (o >= O) return;
    int colblk = o / bnsz, c = o % bnsz;
    const float* ps = psum + (size_t)colblk * npart * bnsz + c;
    const float* pq = psq + (size_t)colblk * npart * bnsz + c;
    float s = 0.f, s2 = 0.f;
    for (int i = 0; i < npart; i++) {
        s  += ps[(size_t)i * bnsz];
        s2 += pq[(size_t)i * bnsz];
    }
    float mu = s * cnt_inv;
    float var = s2 * cnt_inv - mu * mu;
    mean[o] = mu;
    rstd[o] = rsqrtf(var + 1e-5f);
}

__global__ void diag_kernel(const float* __restrict__ G, float* __restrict__ sq)
{
    int bn = blockIdx.x * blockDim.x + threadIdx.x;
    if (bn < NPTS) {
        int b = bn >> 11, n = bn & 2047;
        sq[bn] = G[((size_t)b * NN + n) * NN + n];
    }
}

// ---------------- kNN select core (cached per-thread argmax) ----------------
#define KNN_SELECT_BODY(dist, out, bn)                                           \
    {                                                                            \
        float bv = -FLT_MAX; int bi = 0x7fffffff;                                \
        _Pragma("unroll")                                                        \
        for (int u2 = 0; u2 < NN / 256; u2++) {                                  \
            int j = u2 * 256 + tid;                                              \
            float v = dist[j];                                                   \
            if (v > bv) { bv = v; bi = j; }                                      \
        }                                                                        \
        for (int sel = 0; sel < KK; sel++) {                                     \
            float cv = bv; int ci = bi;                                          \
            _Pragma("unroll")                                                    \
            for (int off = 16; off > 0; off >>= 1) {                             \
                float ov = __shfl_down_sync(0xffffffffu, cv, off);               \
                int oi = __shfl_down_sync(0xffffffffu, ci, off);                 \
                if (ov > cv || (ov == cv && oi < ci)) { cv = ov; ci = oi; }      \
            }                                                                    \
            if (lane == 0) { wv[warp] = cv; wi[warp] = ci; }                     \
            __syncthreads();                                                     \
            if (tid == 0) {                                                      \
                float fv = wv[0]; int fi = wi[0];                                \
                _Pragma("unroll")                                                \
                for (int w = 1; w < 8; w++)                                      \
                    if (wv[w] > fv || (wv[w] == fv && wi[w] < fi)) {             \
                        fv = wv[w]; fi = wi[w];                                  \
                    }                                                            \
                out[(bn) * KK + sel] = fi;                                       \
                sfi = fi;                                                        \
            }                                                                    \
            __syncthreads();                                                     \
            int fi = sfi;                                                        \
            if ((fi & 255) == tid) {                                             \
                dist[fi] = -FLT_MAX;                                             \
                bv = -FLT_MAX; bi = 0x7fffffff;                                  \
                _Pragma("unroll")                                                \
                for (int u2 = 0; u2 < NN / 256; u2++) {                          \
                    int j = u2 * 256 + tid;                                      \
                    float v = dist[j];                                           \
                    if (v > bv) { bv = v; bi = j; }                              \
                }                                                                \
            }                                                                    \
        }                                                                        \
    }

__global__ void knn_select(const float* __restrict__ G, const float* __restrict__ sq,
                           int* __restrict__ out)
{
    int bn = blockIdx.x;
    int b = bn >> 11, n = bn & 2047;
    __shared__ float dist[NN];
    __shared__ float wv[8];
    __shared__ int wi[8];
    __shared__ int sfi;
    int tid = threadIdx.x;
    int lane = tid & 31, warp = tid >> 5;
    const float* row = G + ((size_t)b * NN + n) * NN;
    const float* sqb = sq + (b << 11);
    float sqn = sqb[n];
    for (int j = tid; j < NN; j += 256)
        dist[j] = 2.f * row[j] - sqn - sqb[j];
    __syncthreads();
    KNN_SELECT_BODY(dist, out, bn)
}

__global__ void knn_xyz(const float* __restrict__ x, int* __restrict__ out)
{
    int bn = blockIdx.x;
    int b = bn >> 11, n = bn & 2047;
    __shared__ float dist[NN];
    __shared__ float sx[NN], sy[NN], sz[NN], ssq[NN];
    __shared__ float wv[8];
    __shared__ int wi[8];
    __shared__ int sfi;
    int tid = threadIdx.x;
    int lane = tid & 31, warp = tid >> 5;
    const float* xb = x + (size_t)(b << 11) * 3;
    for (int j = tid; j < NN; j += 256) {
        float xv = xb[j * 3 + 0], yv = xb[j * 3 + 1], zv = xb[j * 3 + 2];
        sx[j] = xv; sy[j] = yv; sz[j] = zv;
        float s = 0.f;
        s = __fmaf_rn(xv, xv, s);
        s = __fmaf_rn(yv, yv, s);
        s = __fmaf_rn(zv, zv, s);
        ssq[j] = s;
    }
    __syncthreads();
    float xi = sx[n], yi = sy[n], zi = sz[n];
    float sqn = ssq[n];
    for (int j = tid; j < NN; j += 256) {
        float s = 0.f;
        s = __fmaf_rn(xi, sx[j], s);
        s = __fmaf_rn(yi, sy[j], s);
        s = __fmaf_rn(zi, sz[j], s);
        dist[j] = 2.f * s - sqn - ssq[j];
    }
    __syncthreads();
    KNN_SELECT_BODY(dist, out, bn)
}

// ---------------- conv5 BN partials ----------------
__global__ void bn5_partial(const float* __restrict__ y5, float* __restrict__ psum,
                            float* __restrict__ psq)
{
    int blk = blockIdx.x;
    int t0 = blk * 256;
    int tid = threadIdx.x;
    float s[4] = {0, 0, 0, 0}, s2[4] = {0, 0, 0, 0};
    for (int t = t0; t < t0 + 256; t++) {
        const float* row = y5 + (size_t)t * DD;
#pragma unroll
        for (int i = 0; i < 4; i++) {
            float v = row[tid + i * 256];
            s[i] += v; s2[i] += v * v;
        }
    }
#pragma unroll
    for (int i = 0; i < 4; i++) {
        psum[(size_t)blk * DD + tid + i * 256] = s[i];
        psq[(size_t)blk * DD + tid + i * 256] = s2[i];
    }
}

// ---------------- BN5 + leaky + patch max-pool + cls ----------------
__global__ void pool_kernel(const float* __restrict__ y5, const float* __restrict__ mean,
                            const float* __restrict__ rstd, const float* __restrict__ g5,
                            const float* __restrict__ b5, const float* __restrict__ cls,
                            float* __restrict__ t)
{
    int tok = blockIdx.x;
    int b = tok / 65, l = tok - b * 65;
    int tid = threadIdx.x;
    if (l == 0) {
        for (int d = tid; d < DD; d += 256) t[(size_t)tok * DD + d] = cls[d];
    } else {
        int p = l - 1;
        int base = b * NN + p * PS;
        for (int d = tid; d < DD; d += 256) {
            float mu = mean[d], rs = rstd[d], gg = g5[d], bb = b5[d];
            float m = -FLT_MAX;
            for (int s = 0; s < PS; s++) {
                float v = y5[(size_t)(base + s) * DD + d];
                v = (v - mu) * rs * gg + bb;
                v = (v >= 0.f) ? v : 0.2f * v;
                m = fmaxf(m, v);
            }
            t[(size_t)tok * DD + d] = m;
        }
    }
}

// ---------------- LayerNorm (optional fused pos-add) ----------------
__global__ void ln_kernel(float* __restrict__ t, const float* __restrict__ pos,
                          const float* __restrict__ g, const float* __restrict__ b,
                          float* __restrict__ out)
{
    int tok = blockIdx.x, tid = threadIdx.x;
    __shared__ float rs1[256], rs2[256];
    float* trow = t + (size_t)tok * DD;
    float loc[4];
    float s = 0.f, s2 = 0.f;
#pragma unroll
    for (int i = 0; i < 4; i++) {
        int d = tid + i * 256;
        float v = trow[d];
        if (pos) { v += pos[(size_t)tok * DD + d]; trow[d] = v; }
        loc[i] = v; s += v; s2 += v * v;
    }
    rs1[tid] = s; rs2[tid] = s2;
    __syncthreads();
    for (int st = 128; st > 0; st >>= 1) {
        if (tid < st) { rs1[tid] += rs1[tid + st]; rs2[tid] += rs2[tid + st]; }
        __syncthreads();
    }
    float mean = rs1[0] * (1.f / DD);
    float var = rs2[0] * (1.f / DD) - mean * mean;
    float rstd = rsqrtf(var + 1e-5f);
#pragma unroll
    for (int i = 0; i < 4; i++) {
        int d = tid + i * 256;
        out[(size_t)tok * DD + d] = (loc[i] - mean) * rstd * g[d] + b[d];
    }
}

// ---------------- attention ----------------
__global__ void attn_kernel(const float* __restrict__ qkv, float* __restrict__ z)
{
    int l = blockIdx.x, hh = blockIdx.y, b = blockIdx.z;
    int tid = threadIdx.x;   // 128
    __shared__ float sq_[64];
    __shared__ float sc[65];
    __shared__ float sinv;
    const float* qrow = qkv + (size_t)(b * 65 + l) * 1536 + hh * 64;
    if (tid < 64) sq_[tid] = qrow[tid];
    __syncthreads();
    if (tid < 65) {
        const float* krow = qkv + (size_t)(b * 65 + tid) * 1536 + 512 + hh * 64;
        float s = 0.f;
#pragma unroll 16
        for (int d = 0; d < 64; d++) s += sq_[d] * krow[d];
        sc[tid] = s * 0.125f;
    }
    __syncthreads();
    if (tid == 0) {
        float mx = -FLT_MAX;
        for (int m = 0; m < 65; m++) mx = fmaxf(mx, sc[m]);
        float sum = 0.f;
        for (int m = 0; m < 65; m++) { float e = expf(sc[m] - mx); sc[m] = e; sum += e; }
        sinv = 1.f / sum;
    }
    __syncthreads();
    if (tid < 64) {
        float inv = sinv;
        float acc = 0.f;
        for (int m = 0; m < 65; m++) {
            const float* vrow = qkv + (size_t)(b * 65 + m) * 1536 + 1024 + hh * 64;
            acc += sc[m] * vrow[tid];
        }
        z[(size_t)(b * 65 + l) * INNER + hh * 64 + tid] = acc * inv;
    }
}

__global__ void out_copy(const float* __restrict__ t, float* __restrict__ out)
{
    int i = blockIdx.x * blockDim.x + threadIdx.x;
    if (i < BB * PP * DD) {
        int d = i & (DD - 1);
        int bp = i >> 10;
        int b = bp >> 6, p = bp & 63;
        out[i] = t[((size_t)(b * 65 + 1 + p) << 10) + d];
    }
}

// ---------------- host driver ----------------
static void edge_layer(const float* featPtr, int lda, int C,
                       const float* w, const float* g, const float* b,
                       int O, int outOff, bool first, const float* xyz,
                       float* h, float* G, float* sq, int* knn,
                       float* u, float* t2, float* umax, float* umin,
                       float* psum, float* psq, float* mean, float* rstd)
{
    if (first) {
        knn_xyz<<<NPTS, 256>>>(xyz, knn);
    } else {
        dim3 gg(NN / 128, NN / 128, BB);
        gemm128<true, 0, false><<<gg, 256>>>(
            featPtr, lda, (size_t)NN * lda, featPtr, lda, (size_t)NN * lda,
            nullptr, G, NN, (size_t)NN * NN, NN, NN, C);
        diag_kernel<<<(NPTS + 255) / 256, 256>>>(G, sq);
        knn_select<<<NPTS, 256>>>(G, sq, knn);
    }
    int C2 = 2 * C;
    // u = feat . w[:, :C]^T ; t2 = feat . w[:, C:2C]^T   (M=16384, N=O, K=C)
    dim3 gu((O + 127) / 128, NPTS / 128);
    gemm128<true, 0, false><<<gu, 256>>>(featPtr, lda, 0, w, C2, 0, nullptr,
                                         u, O, 0, NPTS, O, C);
    gemm128<true, 0, false><<<gu, 256>>>(featPtr, lda, 0, w + C, C2, 0, nullptr,
                                         t2, O, 0, NPTS, O, C);
    ec_uv_stats<<<NPTS / 32, O>>>(u, t2, knn, O, umax, umin, psum, psq);
    bn_reduce2<<<(O + 255) / 256, 256>>>(psum, psq, NPTS / 32, O, O,
                                         1.f / (float)EROWS, mean, rstd);
    ec_apply_uv<<<NPTS * O / 256, 256>>>(u, t2, umax, umin, mean, rstd, g, b,
                                         h, outOff, O);
}

extern "C" void kernel_launch(void* const* d_in, const int* in_sizes, int n_in,
                              void* d_out, int out_size)
{
    const float* x      = (const float*)d_in[0];
    const float* pos    = (const float*)d_in[1];
    const float* w1 = (const float*)d_in[2];  const float* g1 = (const float*)d_in[3];  const float* b1 = (const float*)d_in[4];
    const float* w2 = (const float*)d_in[5];  const float* g2 = (const float*)d_in[6];  const float* b2 = (const float*)d_in[7];
    const float* w3 = (const float*)d_in[8];  const float* g3 = (const float*)d_in[9];  const float* b3 = (const float*)d_in[10];
    const float* w4 = (const float*)d_in[11]; const float* g4 = (const float*)d_in[12]; const float* b4 = (const float*)d_in[13];
    const float* w5 = (const float*)d_in[14]; const float* g5 = (const float*)d_in[15]; const float* b5 = (const float*)d_in[16];
    const float* cls    = (const float*)d_in[17];
    const float* ln1g   = (const float*)d_in[18];
    const float* ln1b   = (const float*)d_in[19];
    const float* wqkv   = (const float*)d_in[20];
    const float* wout   = (const float*)d_in[21];
    const float* bout   = (const float*)d_in[22];
    const float* ln2g   = (const float*)d_in[23];
    const float* ln2b   = (const float*)d_in[24];
    const float* wff1   = (const float*)d_in[25];
    const float* bff1   = (const float*)d_in[26];
    const float* wff2   = (const float*)d_in[27];
    const float* bff2   = (const float*)d_in[28];
    float* out = (float*)d_out;

    float *h, *G, *sq, *u, *t2, *umax, *umin, *psum, *psq, *mean, *rstd;
    float *y5, *t, *ln, *qkv, *z, *ff;
    int* knn;
    cudaGetSymbolAddress((void**)&h, g_h);
    cudaGetSymbolAddress((void**)&G, g_G);
    cudaGetSymbolAddress((void**)&sq, g_sq);
    cudaGetSymbolAddress((void**)&knn, g_knn);
    cudaGetSymbolAddress((void**)&u, g_u);
    cudaGetSymbolAddress((void**)&t2, g_t2);
    cudaGetSymbolAddress((void**)&umax, g_umax);
    cudaGetSymbolAddress((void**)&umin, g_umin);
    cudaGetSymbolAddress((void**)&psum, g_psum);
    cudaGetSymbolAddress((void**)&psq, g_psq);
    cudaGetSymbolAddress((void**)&mean, g_mean);
    cudaGetSymbolAddress((void**)&rstd, g_rstd);
    cudaGetSymbolAddress((void**)&y5, g_y5);
    cudaGetSymbolAddress((void**)&t, g_t);
    cudaGetSymbolAddress((void**)&ln, g_ln);
    cudaGetSymbolAddress((void**)&qkv, g_qkv);
    cudaGetSymbolAddress((void**)&z, g_z);
    cudaGetSymbolAddress((void**)&ff, g_ff);

    // ---- DGCNN backbone (factorized EdgeConv) ----
    edge_layer(x,       3,   3,   w1, g1, b1, 64,  0,   true,  x,
               h, G, sq, knn, u, t2, umax, umin, psum, psq, mean, rstd);
    edge_layer(h + 0,   512, 64,  w2, g2, b2, 64,  64,  false, nullptr,
               h, G, sq, knn, u, t2, umax, umin, psum, psq, mean, rstd);
    edge_layer(h + 64,  512, 64,  w3, g3, b3, 128, 128, false, nullptr,
               h, G, sq, knn, u, t2, umax, umin, psum, psq, mean, rstd);
    edge_layer(h + 128, 512, 128, w4, g4, b4, 256, 256, false, nullptr,
               h, G, sq, knn, u, t2, umax, umin, psum, psq, mean, rstd);

    // ---- conv5 ----
    {
        dim3 gg(DD / 128, NPTS / 128);
        gemm128<true, 0, false><<<gg, 256>>>(
            h, 512, 0, w5, 512, 0, nullptr, y5, DD, 0, NPTS, DD, 512);
        bn5_partial<<<NPTS / 256, 256>>>(y5, psum, psq);
        bn_reduce2<<<(DD + 255) / 256, 256>>>(psum, psq, NPTS / 256, DD, DD,
                                              1.f / (8.f * 2048.f), mean, rstd);
        pool_kernel<<<TOK, 256>>>(y5, mean, rstd, g5, b5, cls, t);
    }

    // ---- transformer ----
    for (int i = 0; i < 6; i++) {
        const float* wqkv_i = wqkv + (size_t)i * DD * 3 * INNER;
        const float* wout_i = wout + (size_t)i * INNER * DD;
        const float* bout_i = bout + (size_t)i * DD;
        const float* wff1_i = wff1 + (size_t)i * DD * MLPD;
        const float* bff1_i = bff1 + (size_t)i * MLPD;
        const float* wff2_i = wff2 + (size_t)i * MLPD * DD;
        const float* bff2_i = bff2 + (size_t)i * DD;

        ln_kernel<<<TOK, 256>>>(t, pos, ln1g + i * DD, ln1b + i * DD, ln);

        dim3 gq(3 * INNER / 64, (TOK + 63) / 64);
        gemm64<0, false><<<gq, 256>>>(ln, DD, wqkv_i, 3 * INNER, nullptr,
                                      qkv, 3 * INNER, TOK, 3 * INNER, DD);

        attn_kernel<<<dim3(65, 8, BB), 128>>>(qkv, z);

        dim3 gp(DD / 64, (TOK + 63) / 64);
        gemm64<0, true><<<gp, 256>>>(z, INNER, wout_i, DD, bout_i,
                                     t, DD, TOK, DD, INNER);

        ln_kernel<<<TOK, 256>>>(t, nullptr, ln2g + i * DD, ln2b + i * DD, ln);

        dim3 gf1(MLPD / 64, (TOK + 63) / 64);
        gemm64<1, false><<<gf1, 256>>>(ln, DD, wff1_i, MLPD, bff1_i,
                                       ff, MLPD, TOK, MLPD, DD);

        dim3 gf2(DD / 64, (TOK + 63) / 64);
        gemm64<0, true><<<gf2, 256>>>(ff, MLPD, wff2_i, DD, bff2_i,
                                      t, DD, TOK, DD, MLPD);
    }

    out_copy<<<(BB * PP * DD + 255) / 256, 256>>>(t, out);
}